// round 13
// baseline (speedup 1.0000x reference)
#include <cuda_runtime.h>
#include <cuda_bf16.h>
#include <math.h>

// ---------------- problem constants ----------------
#define Bb   4
#define Ll   1024
#define Dd   512
#define Hh   8
#define Ee   64
#define DINc 1024
#define Nn   16
#define Rr   32
#define Mrows (Bb*Ll)          // 4096
#define QLD  1536              // fused qkv row stride

// ---------------- fp32 scratch ----------------
__device__ float g_t1[Mrows*Dd];
__device__ float g_x1[Mrows*Dd];
__device__ float g_xz[(size_t)Mrows*2*DINc];
__device__ float g_xc[(size_t)Mrows*DINc];
__device__ float g_db[Mrows*64];
__device__ float g_dt[(size_t)Mrows*DINc];
__device__ float g_y [Mrows*Dd];
__device__ float g_bqkv[3*Dd];

// ---------------- bf16 pair scratch (hi/lo) ----------------
__device__ __nv_bfloat16 g_xh [Mrows*Dd],   g_xl [Mrows*Dd];
__device__ __nv_bfloat16 g_qkvh[(size_t)Mrows*QLD], g_qkvl[(size_t)Mrows*QLD];
__device__ __nv_bfloat16 g_vth[(size_t)Bb*Hh*Ee*Ll], g_vtl[(size_t)Bb*Hh*Ee*Ll];
__device__ __nv_bfloat16 g_ah [(size_t)Bb*Hh*Ll*Ll], g_al [(size_t)Bb*Hh*Ll*Ll];
__device__ __nv_bfloat16 g_oh [Mrows*Dd],   g_ol [Mrows*Dd];
__device__ __nv_bfloat16 g_x1h[Mrows*Dd],   g_x1l[Mrows*Dd];
__device__ __nv_bfloat16 g_yah[(size_t)Mrows*DINc], g_yal[(size_t)Mrows*DINc];
// transposed weights [N][K]
__device__ __nv_bfloat16 g_Wqkvh[(size_t)3*Dd*Dd], g_Wqkvl[(size_t)3*Dd*Dd];
__device__ __nv_bfloat16 g_Woh[Dd*Dd],  g_Wol[Dd*Dd];
__device__ __nv_bfloat16 g_Wih[(size_t)Dd*2*DINc], g_Wil[(size_t)Dd*2*DINc];
__device__ __nv_bfloat16 g_Wuh[(size_t)DINc*Dd],   g_Wul[(size_t)DINc*Dd];

// ---------------- helpers ----------------
__device__ __forceinline__ unsigned sptr(const void* p){
    unsigned a;
    asm("{ .reg .u64 t; cvta.to.shared.u64 t, %1; cvt.u32.u64 %0, t; }" : "=r"(a) : "l"(p));
    return a;
}
__device__ __forceinline__ void ldm_x4(unsigned* f, unsigned addr){
    asm volatile("ldmatrix.sync.aligned.m8n8.x4.shared.b16 {%0,%1,%2,%3}, [%4];"
        : "=r"(f[0]), "=r"(f[1]), "=r"(f[2]), "=r"(f[3]) : "r"(addr));
}
__device__ __forceinline__ void mma16816(float* d, const unsigned* a,
                                         unsigned b0, unsigned b1){
    asm volatile(
        "mma.sync.aligned.m16n8k16.row.col.f32.bf16.bf16.f32 "
        "{%0,%1,%2,%3}, {%4,%5,%6,%7}, {%8,%9}, {%0,%1,%2,%3};"
        : "+f"(d[0]), "+f"(d[1]), "+f"(d[2]), "+f"(d[3])
        : "r"(a[0]), "r"(a[1]), "r"(a[2]), "r"(a[3]), "r"(b0), "r"(b1));
}
__device__ __forceinline__ void split2(float v, __nv_bfloat16& h, __nv_bfloat16& l){
    h = __float2bfloat16(v);
    l = __float2bfloat16(v - __bfloat162float(h));
}

// ====== unified 3x-split tensor-core GEMM, double-buffered (BK=16) ========
// C[M,N] = (Ah+Al)[M,K] @ (Bh+Bl)^T, B stored [N][K] stride K.
// A row stride = lda. Output pair (Ch/Cl) or fp32 (Cf), stride ldc.
__global__ __launch_bounds__(256) void gemm_mma(
    const __nv_bfloat16* __restrict__ Ah, const __nv_bfloat16* __restrict__ Al,
    const __nv_bfloat16* __restrict__ Bh, const __nv_bfloat16* __restrict__ Bl,
    const float* __restrict__ bias,
    float* __restrict__ Cf, __nv_bfloat16* __restrict__ Ch,
    __nv_bfloat16* __restrict__ Cl, int lda, int ldc, int K)
{
    __shared__ __nv_bfloat16 sAh[2][128][24], sAl[2][128][24];
    __shared__ __nv_bfloat16 sBh[2][128][24], sBl[2][128][24];
    const int tid = threadIdx.x;
    const int wid = tid >> 5, lane = tid & 31;
    const int row0 = blockIdx.y * 128, col0 = blockIdx.x * 128;
    const int wm = (wid & 3) * 32;
    const int wn = (wid >> 2) * 64;

    float acc[2][8][4];
#pragma unroll
    for (int i=0;i<2;i++)
#pragma unroll
        for (int j=0;j<8;j++)
#pragma unroll
            for (int t=0;t<4;t++) acc[i][j][t]=0.f;

    const int lr = lane & 15, lh = (lane >> 4) * 8;
    const int sr = tid & 127, sc = (tid >> 7) * 8;
    const long aoff = (long)(row0 + sr) * lda + sc;
    const long boff = (long)(col0 + sr) * K + sc;

    uint4 r0, r1, r2, r3;
    r0 = *(const uint4*)(Ah + aoff);
    r1 = *(const uint4*)(Al + aoff);
    r2 = *(const uint4*)(Bh + boff);
    r3 = *(const uint4*)(Bl + boff);
    *(uint4*)&sAh[0][sr][sc] = r0;
    *(uint4*)&sAl[0][sr][sc] = r1;
    *(uint4*)&sBh[0][sr][sc] = r2;
    *(uint4*)&sBl[0][sr][sc] = r3;
    __syncthreads();

    const int nch = K >> 4;
    for (int c = 0; c < nch; c++) {
        const int buf = c & 1;
        const bool more = (c + 1) < nch;
        if (more) {
            r0 = *(const uint4*)(Ah + aoff + (c+1)*16);
            r1 = *(const uint4*)(Al + aoff + (c+1)*16);
            r2 = *(const uint4*)(Bh + boff + (c+1)*16);
            r3 = *(const uint4*)(Bl + boff + (c+1)*16);
        }
        unsigned ahf[2][4], alf[2][4];
#pragma unroll
        for (int mi = 0; mi < 2; mi++) {
            ldm_x4(ahf[mi], sptr(&sAh[buf][wm + mi*16 + lr][lh]));
            ldm_x4(alf[mi], sptr(&sAl[buf][wm + mi*16 + lr][lh]));
        }
#pragma unroll
        for (int half = 0; half < 2; half++) {
            unsigned bh[4][2], bl[4][2];
#pragma unroll
            for (int p = 0; p < 2; p++) {
                unsigned f[4];
                ldm_x4(f, sptr(&sBh[buf][wn + half*32 + p*16 + lr][lh]));
                bh[2*p+0][0]=f[0]; bh[2*p+0][1]=f[2];
                bh[2*p+1][0]=f[1]; bh[2*p+1][1]=f[3];
                ldm_x4(f, sptr(&sBl[buf][wn + half*32 + p*16 + lr][lh]));
                bl[2*p+0][0]=f[0]; bl[2*p+0][1]=f[2];
                bl[2*p+1][0]=f[1]; bl[2*p+1][1]=f[3];
            }
#pragma unroll
            for (int mi = 0; mi < 2; mi++)
#pragma unroll
                for (int nj = 0; nj < 4; nj++) {
                    float* a = acc[mi][half*4 + nj];
                    mma16816(a, ahf[mi], bh[nj][0], bh[nj][1]);
                    mma16816(a, ahf[mi], bl[nj][0], bl[nj][1]);
                    mma16816(a, alf[mi], bh[nj][0], bh[nj][1]);
                }
        }
        if (more) {
            *(uint4*)&sAh[buf^1][sr][sc] = r0;
            *(uint4*)&sAl[buf^1][sr][sc] = r1;
            *(uint4*)&sBh[buf^1][sr][sc] = r2;
            *(uint4*)&sBl[buf^1][sr][sc] = r3;
        }
        __syncthreads();
    }

#pragma unroll
    for (int mi = 0; mi < 2; mi++) {
        const int r = row0 + wm + mi*16 + (lane >> 2);
#pragma unroll
        for (int ni = 0; ni < 8; ni++) {
            const int c = col0 + wn + (ni>>2)*32 + (ni&3)*8 + (lane & 3)*2;
            float b0 = 0.f, b1 = 0.f;
            if (bias) { b0 = bias[c]; b1 = bias[c+1]; }
            const float v0 = acc[mi][ni][0]+b0, v1 = acc[mi][ni][1]+b1;
            const float v2 = acc[mi][ni][2]+b0, v3 = acc[mi][ni][3]+b1;
            if (Ch) {
                __nv_bfloat162 h2, l2;
                split2(v0, h2.x, l2.x); split2(v1, h2.y, l2.y);
                *(__nv_bfloat162*)(Ch + (long)r*ldc + c) = h2;
                *(__nv_bfloat162*)(Cl + (long)r*ldc + c) = l2;
                split2(v2, h2.x, l2.x); split2(v3, h2.y, l2.y);
                *(__nv_bfloat162*)(Ch + (long)(r+8)*ldc + c) = h2;
                *(__nv_bfloat162*)(Cl + (long)(r+8)*ldc + c) = l2;
            } else {
                *(float2*)(Cf + (long)r*ldc + c)     = make_float2(v0, v1);
                *(float2*)(Cf + (long)(r+8)*ldc + c) = make_float2(v2, v3);
            }
        }
    }
}

// ========== scores via mma (double-buffered): S = q @ k^T * 0.125 ==========
// q,k live in fused qkv pair buffer, row stride QLD; k at col offset Dd.
__global__ __launch_bounds__(256) void scores_mma(
    const __nv_bfloat16* __restrict__ qkvh, const __nv_bfloat16* __restrict__ qkvl,
    float* __restrict__ attn)
{
    __shared__ __nv_bfloat16 sAh[2][128][24], sAl[2][128][24];
    __shared__ __nv_bfloat16 sBh[2][128][24], sBl[2][128][24];
    const int tid = threadIdx.x;
    const int wid = tid >> 5, lane = tid & 31;
    const int bz = blockIdx.z;
    const long abase = (long)(bz>>3)*Ll*QLD + (bz&7)*Ee;
    const long bbase = abase + Dd;
    float* C = attn + (long)bz*Ll*Ll;
    const int row0 = blockIdx.y * 128, col0 = blockIdx.x * 128;
    const int wm = (wid & 3) * 32;
    const int wn = (wid >> 2) * 64;

    float acc[2][8][4];
#pragma unroll
    for (int i=0;i<2;i++)
#pragma unroll
        for (int j=0;j<8;j++)
#pragma unroll
            for (int t=0;t<4;t++) acc[i][j][t]=0.f;

    const int lr = lane & 15, lh = (lane >> 4) * 8;
    const int sr = tid & 127, sc = (tid >> 7) * 8;
    const long aoff = abase + (long)(row0 + sr) * QLD + sc;
    const long boff = bbase + (long)(col0 + sr) * QLD + sc;

    uint4 r0, r1, r2, r3;
    r0 = *(const uint4*)(qkvh + aoff);
    r1 = *(const uint4*)(qkvl + aoff);
    r2 = *(const uint4*)(qkvh + boff);
    r3 = *(const uint4*)(qkvl + boff);
    *(uint4*)&sAh[0][sr][sc] = r0;
    *(uint4*)&sAl[0][sr][sc] = r1;
    *(uint4*)&sBh[0][sr][sc] = r2;
    *(uint4*)&sBl[0][sr][sc] = r3;
    __syncthreads();

    const int nch = Ee >> 4;   // 4
    for (int c = 0; c < nch; c++) {
        const int buf = c & 1;
        const bool more = (c + 1) < nch;
        if (more) {
            r0 = *(const uint4*)(qkvh + aoff + (c+1)*16);
            r1 = *(const uint4*)(qkvl + aoff + (c+1)*16);
            r2 = *(const uint4*)(qkvh + boff + (c+1)*16);
            r3 = *(const uint4*)(qkvl + boff + (c+1)*16);
        }
        unsigned ahf[2][4], alf[2][4];
#pragma unroll
        for (int mi = 0; mi < 2; mi++) {
            ldm_x4(ahf[mi], sptr(&sAh[buf][wm + mi*16 + lr][lh]));
            ldm_x4(alf[mi], sptr(&sAl[buf][wm + mi*16 + lr][lh]));
        }
#pragma unroll
        for (int half = 0; half < 2; half++) {
            unsigned bh[4][2], bl[4][2];
#pragma unroll
            for (int p = 0; p < 2; p++) {
                unsigned f[4];
                ldm_x4(f, sptr(&sBh[buf][wn + half*32 + p*16 + lr][lh]));
                bh[2*p+0][0]=f[0]; bh[2*p+0][1]=f[2];
                bh[2*p+1][0]=f[1]; bh[2*p+1][1]=f[3];
                ldm_x4(f, sptr(&sBl[buf][wn + half*32 + p*16 + lr][lh]));
                bl[2*p+0][0]=f[0]; bl[2*p+0][1]=f[2];
                bl[2*p+1][0]=f[1]; bl[2*p+1][1]=f[3];
            }
#pragma unroll
            for (int mi = 0; mi < 2; mi++)
#pragma unroll
                for (int nj = 0; nj < 4; nj++) {
                    float* a = acc[mi][half*4 + nj];
                    mma16816(a, ahf[mi], bh[nj][0], bh[nj][1]);
                    mma16816(a, ahf[mi], bl[nj][0], bl[nj][1]);
                    mma16816(a, alf[mi], bh[nj][0], bh[nj][1]);
                }
        }
        if (more) {
            *(uint4*)&sAh[buf^1][sr][sc] = r0;
            *(uint4*)&sAl[buf^1][sr][sc] = r1;
            *(uint4*)&sBh[buf^1][sr][sc] = r2;
            *(uint4*)&sBl[buf^1][sr][sc] = r3;
        }
        __syncthreads();
    }

#pragma unroll
    for (int mi = 0; mi < 2; mi++) {
        const int r = row0 + wm + mi*16 + (lane >> 2);
#pragma unroll
        for (int ni = 0; ni < 8; ni++) {
            const int c = col0 + wn + (ni>>2)*32 + (ni&3)*8 + (lane & 3)*2;
            *(float2*)(C + (long)r*Ll + c) =
                make_float2(acc[mi][ni][0]*0.125f, acc[mi][ni][1]*0.125f);
            *(float2*)(C + (long)(r+8)*Ll + c) =
                make_float2(acc[mi][ni][2]*0.125f, acc[mi][ni][3]*0.125f);
        }
    }
}

// ====== attn @ v via mma (double-buffered): per (b,h), BM=128, BN=64 =======
__global__ __launch_bounds__(256) void attnv_mma(
    const __nv_bfloat16* __restrict__ ah, const __nv_bfloat16* __restrict__ al,
    const __nv_bfloat16* __restrict__ vth, const __nv_bfloat16* __restrict__ vtl,
    __nv_bfloat16* __restrict__ oh, __nv_bfloat16* __restrict__ ol)
{
    __shared__ __nv_bfloat16 sAh[2][128][24], sAl[2][128][24];
    __shared__ __nv_bfloat16 sBh[2][64][24],  sBl[2][64][24];
    const int tid = threadIdx.x;
    const int wid = tid >> 5, lane = tid & 31;
    const int bz = blockIdx.z;
    const __nv_bfloat16* Abh = ah + (long)bz*Ll*Ll;
    const __nv_bfloat16* Abl = al + (long)bz*Ll*Ll;
    const __nv_bfloat16* Bbh = vth + (long)bz*Ee*Ll;
    const __nv_bfloat16* Bbl = vtl + (long)bz*Ee*Ll;
    const long obase = (long)(bz>>3)*Ll*Dd + (bz&7)*Ee;
    const int row0 = blockIdx.y * 128;
    const int wm = (wid & 3) * 32;
    const int wn = (wid >> 2) * 32;

    float acc[2][4][4];
#pragma unroll
    for (int i=0;i<2;i++)
#pragma unroll
        for (int j=0;j<4;j++)
#pragma unroll
            for (int t=0;t<4;t++) acc[i][j][t]=0.f;

    const int lr = lane & 15, lh = (lane >> 4) * 8;
    const int sr = tid & 127, sc = (tid >> 7) * 8;
    const long aoff = (long)(row0 + sr) * Ll + sc;
    const int  br = tid & 63, bcc = ((tid >> 6) & 1) * 8;   // tid<128 stages B
    const long boff = (long)br * Ll + bcc;

    uint4 r0, r1, r2, r3;
    r0 = *(const uint4*)(Abh + aoff);
    r1 = *(const uint4*)(Abl + aoff);
    if (tid < 128) {
        r2 = *(const uint4*)(Bbh + boff);
        r3 = *(const uint4*)(Bbl + boff);
    }
    *(uint4*)&sAh[0][sr][sc] = r0;
    *(uint4*)&sAl[0][sr][sc] = r1;
    if (tid < 128) {
        *(uint4*)&sBh[0][br][bcc] = r2;
        *(uint4*)&sBl[0][br][bcc] = r3;
    }
    __syncthreads();

    const int nch = Ll >> 4;   // 64
    for (int c = 0; c < nch; c++) {
        const int buf = c & 1;
        const bool more = (c + 1) < nch;
        if (more) {
            r0 = *(const uint4*)(Abh + aoff + (c+1)*16);
            r1 = *(const uint4*)(Abl + aoff + (c+1)*16);
            if (tid < 128) {
                r2 = *(const uint4*)(Bbh + boff + (c+1)*16);
                r3 = *(const uint4*)(Bbl + boff + (c+1)*16);
            }
        }
        unsigned ahf[2][4], alf[2][4];
#pragma unroll
        for (int mi = 0; mi < 2; mi++) {
            ldm_x4(ahf[mi], sptr(&sAh[buf][wm + mi*16 + lr][lh]));
            ldm_x4(alf[mi], sptr(&sAl[buf][wm + mi*16 + lr][lh]));
        }
        unsigned bh[4][2], bl[4][2];
#pragma unroll
        for (int p = 0; p < 2; p++) {
            unsigned f[4];
            ldm_x4(f, sptr(&sBh[buf][wn + p*16 + lr][lh]));
            bh[2*p+0][0]=f[0]; bh[2*p+0][1]=f[2];
            bh[2*p+1][0]=f[1]; bh[2*p+1][1]=f[3];
            ldm_x4(f, sptr(&sBl[buf][wn + p*16 + lr][lh]));
            bl[2*p+0][0]=f[0]; bl[2*p+0][1]=f[2];
            bl[2*p+1][0]=f[1]; bl[2*p+1][1]=f[3];
        }
#pragma unroll
        for (int mi = 0; mi < 2; mi++)
#pragma unroll
            for (int nj = 0; nj < 4; nj++) {
                float* a = acc[mi][nj];
                mma16816(a, ahf[mi], bh[nj][0], bh[nj][1]);
                mma16816(a, ahf[mi], bl[nj][0], bl[nj][1]);
                mma16816(a, alf[mi], bh[nj][0], bh[nj][1]);
            }
        if (more) {
            *(uint4*)&sAh[buf^1][sr][sc] = r0;
            *(uint4*)&sAl[buf^1][sr][sc] = r1;
            if (tid < 128) {
                *(uint4*)&sBh[buf^1][br][bcc] = r2;
                *(uint4*)&sBl[buf^1][br][bcc] = r3;
            }
        }
        __syncthreads();
    }

#pragma unroll
    for (int mi = 0; mi < 2; mi++) {
        const int r = row0 + wm + mi*16 + (lane >> 2);
#pragma unroll
        for (int nj = 0; nj < 4; nj++) {
            const int c = wn + nj*8 + (lane & 3)*2;
            __nv_bfloat162 h2, l2;
            split2(acc[mi][nj][0], h2.x, l2.x);
            split2(acc[mi][nj][1], h2.y, l2.y);
            *(__nv_bfloat162*)(oh + obase + (long)r*Dd + c) = h2;
            *(__nv_bfloat162*)(ol + obase + (long)r*Dd + c) = l2;
            split2(acc[mi][nj][2], h2.x, l2.x);
            split2(acc[mi][nj][3], h2.y, l2.y);
            *(__nv_bfloat162*)(oh + obase + (long)(r+8)*Dd + c) = h2;
            *(__nv_bfloat162*)(ol + obase + (long)(r+8)*Dd + c) = l2;
        }
    }
}

// ================= split conversions =======================================
__global__ __launch_bounds__(256) void split_act(
    const float* __restrict__ x, __nv_bfloat16* __restrict__ h,
    __nv_bfloat16* __restrict__ l)
{
    const int i = blockIdx.x * 256 + threadIdx.x;
    const float v = x[i];
    __nv_bfloat16 hi, lo; split2(v, hi, lo);
    h[i] = hi; l[i] = lo;
}

// W [K][N] fp32 -> Wt hi/lo bf16 [N][K]
__global__ __launch_bounds__(256) void split_wt(
    const float* __restrict__ W, int Kdim, int Ndim,
    __nv_bfloat16* __restrict__ h, __nv_bfloat16* __restrict__ l)
{
    __shared__ float t[32][33];
    const int tx = threadIdx.x, ty = threadIdx.y;
    const int n0 = blockIdx.x * 32, k0 = blockIdx.y * 32;
#pragma unroll
    for (int j = 0; j < 4; j++)
        t[ty + 8 * j][tx] = W[(long)(k0 + ty + 8 * j) * Ndim + n0 + tx];
    __syncthreads();
#pragma unroll
    for (int j = 0; j < 4; j++) {
        const float v = t[tx][ty + 8 * j];
        __nv_bfloat16 hi, lo; split2(v, hi, lo);
        const long oidx = (long)(n0 + ty + 8 * j) * Kdim + k0 + tx;
        h[oidx] = hi; l[oidx] = lo;
    }
}

// v (in fused qkv pair, col offset 2*Dd, row stride QLD) -> vT pair [bh][e][s]
__global__ void vtrans(
    const __nv_bfloat16* __restrict__ qkvh, const __nv_bfloat16* __restrict__ qkvl,
    __nv_bfloat16* __restrict__ vth, __nv_bfloat16* __restrict__ vtl)
{
    __shared__ __nv_bfloat16 th[32][33], tl[32][33];
    const int tx = threadIdx.x, ty = threadIdx.y;   // (32, 8)
    const int bh = blockIdx.z;
    const int b = bh >> 3, h = bh & 7;
    const int s0 = blockIdx.x * 32, e0 = blockIdx.y * 32;
    const long ibase = (long)b*Ll*QLD + 2*Dd + h*Ee;
#pragma unroll
    for (int j = 0; j < 4; j++) {
        const long off = ibase + (long)(s0 + ty + 8*j)*QLD + e0 + tx;
        th[ty+8*j][tx] = qkvh[off];
        tl[ty+8*j][tx] = qkvl[off];
    }
    __syncthreads();
    const long obase = (long)bh*Ee*Ll;
#pragma unroll
    for (int j = 0; j < 4; j++) {
        const long off = obase + (long)(e0 + ty + 8*j)*Ll + s0 + tx;
        vth[off] = th[tx][ty+8*j];
        vtl[off] = tl[tx][ty+8*j];
    }
}

// ------- softmax rows of 1024 (float4 I/O), in place + bf16 pair output ----
__global__ __launch_bounds__(256) void softmax_split(
    float* __restrict__ a, __nv_bfloat16* __restrict__ ah,
    __nv_bfloat16* __restrict__ al)
{
    const long row = blockIdx.x;
    float* p = a + row * (long)Ll;
    __nv_bfloat16* ph = ah + row * (long)Ll;
    __nv_bfloat16* pl = al + row * (long)Ll;
    const int tid = threadIdx.x;

    float4 v4 = *(float4*)(p + tid * 4);
    float m = fmaxf(fmaxf(v4.x, v4.y), fmaxf(v4.z, v4.w));
#pragma unroll
    for (int off=16; off; off>>=1) m = fmaxf(m, __shfl_xor_sync(0xffffffffu, m, off));
    __shared__ float sm[8], ss[8];
    const int w = tid >> 5, lane = tid & 31;
    if (lane==0) sm[w] = m;
    __syncthreads();
    m = sm[0];
#pragma unroll
    for (int i=1;i<8;i++) m = fmaxf(m, sm[i]);
    v4.x = __expf(v4.x - m); v4.y = __expf(v4.y - m);
    v4.z = __expf(v4.z - m); v4.w = __expf(v4.w - m);
    float s = v4.x + v4.y + v4.z + v4.w;
#pragma unroll
    for (int off=16; off; off>>=1) s += __shfl_xor_sync(0xffffffffu, s, off);
    if (lane==0) ss[w] = s;
    __syncthreads();
    s = 0.f;
#pragma unroll
    for (int i=0;i<8;i++) s += ss[i];
    const float inv = 1.f / s;
    v4.x *= inv; v4.y *= inv; v4.z *= inv; v4.w *= inv;
    *(float4*)(p + tid * 4) = v4;
    __nv_bfloat162 h01, l01, h23, l23;
    split2(v4.x, h01.x, l01.x); split2(v4.y, h01.y, l01.y);
    split2(v4.z, h23.x, l23.x); split2(v4.w, h23.y, l23.y);
    *(__nv_bfloat162*)(ph + tid*4)     = h01;
    *(__nv_bfloat162*)(ph + tid*4 + 2) = h23;
    *(__nv_bfloat162*)(pl + tid*4)     = l01;
    *(__nv_bfloat162*)(pl + tid*4 + 2) = l23;
}

// ---------------- out = LayerNorm(xa + xb) (+ optional bf16 pair) ----------
__global__ __launch_bounds__(128) void add_ln(
    const float* __restrict__ xa, const float* __restrict__ xb,
    const float* __restrict__ g, const float* __restrict__ bt,
    float* __restrict__ out, __nv_bfloat16* __restrict__ oh,
    __nv_bfloat16* __restrict__ ol)
{
    const int row = blockIdx.x, tid = threadIdx.x;
    const float* pa = xa + (long)row*Dd;
    const float* pb = xb + (long)row*Dd;
    float v[4]; float s1=0.f, s2=0.f;
#pragma unroll
    for (int i=0;i<4;i++){ int c = tid + 128*i; v[i] = pa[c] + pb[c]; s1 += v[i]; s2 += v[i]*v[i]; }
#pragma unroll
    for (int off=16; off; off>>=1){
        s1 += __shfl_xor_sync(0xffffffffu, s1, off);
        s2 += __shfl_xor_sync(0xffffffffu, s2, off);
    }
    __shared__ float r1[4], r2[4];
    const int w = tid >> 5, lane = tid & 31;
    if (lane==0){ r1[w]=s1; r2[w]=s2; }
    __syncthreads();
    s1 = r1[0]+r1[1]+r1[2]+r1[3];
    s2 = r2[0]+r2[1]+r2[2]+r2[3];
    const float mean = s1 * (1.f/Dd);
    const float var  = s2 * (1.f/Dd) - mean*mean;
    const float rstd = rsqrtf(var + 1e-5f);
    float* po = out + (long)row*Dd;
#pragma unroll
    for (int i=0;i<4;i++){
        const int c = tid + 128*i;
        const float val = (v[i]-mean)*rstd*g[c] + bt[c];
        po[c] = val;
        if (oh) {
            __nv_bfloat16 hi, lo; split2(val, hi, lo);
            oh[(long)row*Dd + c] = hi;
            ol[(long)row*Dd + c] = lo;
        }
    }
}

// ============ 64x64 GEMM for small N problems (Wx, Wdt) ====================
__global__ __launch_bounds__(256) void gemm64(
    const float* __restrict__ A, int lda,
    const float* __restrict__ W, int ldw,
    const float* __restrict__ bias,
    float* __restrict__ C, int ldc, int K, int act)
{
    __shared__ float As[16][64];
    __shared__ float Ws[16][68];
    const int tid = threadIdx.x;
    const int row0 = blockIdx.y * 64;
    const int col0 = blockIdx.x * 64;
    const int ar = tid >> 2, ac = (tid & 3) * 4;
    const int br = tid >> 4, bc = (tid & 15) * 4;
    const int tm = (tid & 15) * 4, tn = (tid >> 4) * 4;
    float acc[4][4];
#pragma unroll
    for (int i=0;i<4;i++)
#pragma unroll
        for (int j=0;j<4;j++) acc[i][j]=0.f;

    for (int k0 = 0; k0 < K; k0 += 16) {
        float4 a4 = *(const float4*)(A + (long)(row0+ar)*lda + k0 + ac);
        As[ac+0][ar]=a4.x; As[ac+1][ar]=a4.y; As[ac+2][ar]=a4.z; As[ac+3][ar]=a4.w;
        float4 b4 = *(const float4*)(W + (long)(k0+br)*ldw + col0 + bc);
        *(float4*)&Ws[br][bc] = b4;
        __syncthreads();
#pragma unroll
        for (int k=0;k<16;k++){
            float a[4], b[4];
#pragma unroll
            for (int i=0;i<4;i++) a[i]=As[k][tm+i];
#pragma unroll
            for (int j=0;j<4;j++) b[j]=Ws[k][tn+j];
#pragma unroll
            for (int i=0;i<4;i++)
#pragma unroll
                for (int j=0;j<4;j++) acc[i][j]=fmaf(a[i],b[j],acc[i][j]);
        }
        __syncthreads();
    }
#pragma unroll
    for (int j=0;j<4;j++){
        int c = col0 + tn + j;
        float bvv = bias ? bias[c] : 0.f;
#pragma unroll
        for (int i=0;i<4;i++){
            float vv = acc[i][j] + bvv;
            if (act == 1) vv = (vv > 20.f) ? vv : log1pf(__expf(vv));
            C[(long)(row0+tm+i)*ldc + c] = vv;
        }
    }
}

// ---------------- depthwise causal conv (K=4) + bias + silu ----------------
__global__ __launch_bounds__(256) void conv_silu_k(
    const float* __restrict__ xz, const float* __restrict__ w,
    const float* __restrict__ cb, float* __restrict__ xc)
{
    const long idx = (long)blockIdx.x*256 + threadIdx.x;
    const int d = (int)(idx & (DINc-1));
    const long row = idx >> 10;
    const int l = (int)(row & (Ll-1));
    float acc = cb[d];
#pragma unroll
    for (int j=0;j<4;j++) {
        int ll = l - 3 + j;
        if (ll >= 0)
            acc = fmaf(xz[(row-3+j)*(2*DINc) + d], w[d*4+j], acc);
    }
    xc[idx] = acc / (1.f + __expf(-acc));
}

// ---------- selective scan, depth-8 load pipeline, bf16 pair output --------
#define PFD 8
__global__ __launch_bounds__(128) void scan_k(
    const float* __restrict__ dt, const float* __restrict__ xc,
    const float* __restrict__ dbl, const float* __restrict__ xz,
    const float* __restrict__ Alog, const float* __restrict__ Dp,
    __nv_bfloat16* __restrict__ yh, __nv_bfloat16* __restrict__ yl)
{
    const int tid = threadIdx.x;
    const int n  = tid & 15;
    const int dl = tid >> 4;
    const int b  = blockIdx.x >> 7;
    const int d  = (blockIdx.x & 127)*8 + dl;
    const float Aa = -__expf(Alog[d*Nn + n]);
    const float Dv = Dp[d];
    float h = 0.f;
    const long base = (long)b * Ll;

    float rdt[PFD], rxc[PFD], rB[PFD], rC[PFD], rz[PFD];
#pragma unroll
    for (int i = 0; i < PFD; i++) {
        const long r = base + i;
        rdt[i] = dt[r*DINc + d];
        rxc[i] = xc[r*DINc + d];
        rB[i]  = dbl[r*64 + 32 + n];
        rC[i]  = dbl[r*64 + 48 + n];
        rz[i]  = xz[r*(2*DINc) + DINc + d];
    }

    for (int t0 = 0; t0 < Ll; t0 += PFD) {
        float ndt[PFD], nxc[PFD], nB[PFD], nC[PFD], nz[PFD];
        const bool more = (t0 + PFD) < Ll;
        if (more) {
#pragma unroll
            for (int i = 0; i < PFD; i++) {
                const long r = base + t0 + PFD + i;
                ndt[i] = dt[r*DINc + d];
                nxc[i] = xc[r*DINc + d];
                nB[i]  = dbl[r*64 + 32 + n];
                nC[i]  = dbl[r*64 + 48 + n];
                nz[i]  = xz[r*(2*DINc) + DINc + d];
            }
        }
#pragma unroll
        for (int i = 0; i < PFD; i++) {
            const float dA = __expf(rdt[i] * Aa);
            h = fmaf(h, dA, rdt[i] * rxc[i] * rB[i]);
            float p = h * rC[i];
            p += __shfl_xor_sync(0xffffffffu, p, 8);
            p += __shfl_xor_sync(0xffffffffu, p, 4);
            p += __shfl_xor_sync(0xffffffffu, p, 2);
            p += __shfl_xor_sync(0xffffffffu, p, 1);
            if (n == 0) {
                const float sz = rz[i] / (1.f + __expf(-rz[i]));
                const float val = (p + rxc[i] * Dv) * sz;
                __nv_bfloat16 hi, lo; split2(val, hi, lo);
                yh[(base + t0 + i)*DINc + d] = hi;
                yl[(base + t0 + i)*DINc + d] = lo;
            }
        }
        if (more) {
#pragma unroll
            for (int i = 0; i < PFD; i++) {
                rdt[i]=ndt[i]; rxc[i]=nxc[i]; rB[i]=nB[i]; rC[i]=nC[i]; rz[i]=nz[i];
            }
        }
    }
}

// ---------------- launch ----------------------------------------------------
extern "C" void kernel_launch(void* const* d_in, const int* in_sizes, int n_in,
                              void* d_out, int out_size)
{
    const float* x    = (const float*)d_in[0];
    const float* Wq   = (const float*)d_in[1];
    const float* bq   = (const float*)d_in[2];
    const float* Wk   = (const float*)d_in[3];
    const float* bk   = (const float*)d_in[4];
    const float* Wv   = (const float*)d_in[5];
    const float* bv   = (const float*)d_in[6];
    const float* Wo   = (const float*)d_in[7];
    const float* bo   = (const float*)d_in[8];
    const float* ln1g = (const float*)d_in[9];
    const float* ln1b = (const float*)d_in[10];
    const float* ln2g = (const float*)d_in[11];
    const float* ln2b = (const float*)d_in[12];
    const float* Win  = (const float*)d_in[13];
    const float* cw   = (const float*)d_in[14];
    const float* cb   = (const float*)d_in[15];
    const float* Wx   = (const float*)d_in[16];
    const float* Wdt  = (const float*)d_in[17];
    const float* bdt  = (const float*)d_in[18];
    const float* Alog = (const float*)d_in[19];
    const float* Dp   = (const float*)d_in[20];
    const float* Wout = (const float*)d_in[21];

    float* out  = (float*)d_out;
    float* attn = out + (size_t)Bb*Ll*Dd;

    float *t1,*x1,*xz,*xc,*db,*dtb,*y,*bqkv;
    cudaGetSymbolAddress((void**)&t1, g_t1);
    cudaGetSymbolAddress((void**)&x1, g_x1);
    cudaGetSymbolAddress((void**)&xz, g_xz);
    cudaGetSymbolAddress((void**)&xc, g_xc);
    cudaGetSymbolAddress((void**)&db, g_db);
    cudaGetSymbolAddress((void**)&dtb,g_dt);
    cudaGetSymbolAddress((void**)&y,  g_y);
    cudaGetSymbolAddress((void**)&bqkv, g_bqkv);

    __nv_bfloat16 *xh,*xl,*qkvh,*qkvl,*vth,*vtl,*ah,*al,*oh,*ol,*x1h,*x1l,*yah,*yal;
    __nv_bfloat16 *Wqkvh,*Wqkvl,*Woh,*Wol,*Wih,*Wil,*Wuh,*Wul;
    cudaGetSymbolAddress((void**)&xh,   g_xh);   cudaGetSymbolAddress((void**)&xl,   g_xl);
    cudaGetSymbolAddress((void**)&qkvh, g_qkvh); cudaGetSymbolAddress((void**)&qkvl, g_qkvl);
    cudaGetSymbolAddress((void**)&vth,  g_vth);  cudaGetSymbolAddress((void**)&vtl,  g_vtl);
    cudaGetSymbolAddress((void**)&ah,   g_ah);   cudaGetSymbolAddress((void**)&al,   g_al);
    cudaGetSymbolAddress((void**)&oh,   g_oh);   cudaGetSymbolAddress((void**)&ol,   g_ol);
    cudaGetSymbolAddress((void**)&x1h,  g_x1h);  cudaGetSymbolAddress((void**)&x1l,  g_x1l);
    cudaGetSymbolAddress((void**)&yah,  g_yah);  cudaGetSymbolAddress((void**)&yal,  g_yal);
    cudaGetSymbolAddress((void**)&Wqkvh,g_Wqkvh);cudaGetSymbolAddress((void**)&Wqkvl,g_Wqkvl);
    cudaGetSymbolAddress((void**)&Woh,  g_Woh);  cudaGetSymbolAddress((void**)&Wol,  g_Wol);
    cudaGetSymbolAddress((void**)&Wih,  g_Wih);  cudaGetSymbolAddress((void**)&Wil,  g_Wil);
    cudaGetSymbolAddress((void**)&Wuh,  g_Wuh);  cudaGetSymbolAddress((void**)&Wul,  g_Wul);

    // weight conversions (transpose + hi/lo split); qkv fused [1536][512]
    split_wt<<<dim3(Dd/32, Dd/32), dim3(32,8)>>>(Wq, Dd, Dd, Wqkvh,            Wqkvl);
    split_wt<<<dim3(Dd/32, Dd/32), dim3(32,8)>>>(Wk, Dd, Dd, Wqkvh + Dd*Dd,    Wqkvl + Dd*Dd);
    split_wt<<<dim3(Dd/32, Dd/32), dim3(32,8)>>>(Wv, Dd, Dd, Wqkvh + 2*Dd*Dd,  Wqkvl + 2*Dd*Dd);
    split_wt<<<dim3(Dd/32, Dd/32), dim3(32,8)>>>(Wo, Dd, Dd, Woh, Wol);
    split_wt<<<dim3(2*DINc/32, Dd/32), dim3(32,8)>>>(Win, Dd, 2*DINc, Wih, Wil);
    split_wt<<<dim3(Dd/32, DINc/32), dim3(32,8)>>>(Wout, DINc, Dd, Wuh, Wul);
    cudaMemcpyAsync(bqkv,        bq, Dd*sizeof(float), cudaMemcpyDeviceToDevice, 0);
    cudaMemcpyAsync(bqkv + Dd,   bk, Dd*sizeof(float), cudaMemcpyDeviceToDevice, 0);
    cudaMemcpyAsync(bqkv + 2*Dd, bv, Dd*sizeof(float), cudaMemcpyDeviceToDevice, 0);

    // x split + fused QKV (mma, pair output, ldc=1536)
    split_act<<<(Mrows*Dd)/256, 256>>>(x, xh, xl);
    gemm_mma<<<dim3(QLD/128, Mrows/128), 256>>>(xh, xl, Wqkvh, Wqkvl, bqkv,
                                                nullptr, qkvh, qkvl, Dd, QLD, Dd);
    vtrans<<<dim3(Ll/32, Ee/32, Bb*Hh), dim3(32,8)>>>(qkvh, qkvl, vth, vtl);

    // attention
    scores_mma<<<dim3(Ll/128, Ll/128, Bb*Hh), 256>>>(qkvh, qkvl, attn);
    softmax_split<<<Bb*Hh*Ll, 256>>>(attn, ah, al);
    attnv_mma<<<dim3(1, Ll/128, Bb*Hh), 256>>>(ah, al, vth, vtl, oh, ol);

    // o @ Wo + bo (mma) ; x1 = LN(x + .) with pair output
    gemm_mma<<<dim3(Dd/128, Mrows/128), 256>>>(oh, ol, Woh, Wol, bo,
                                               t1, nullptr, nullptr, Dd, Dd, Dd);
    add_ln<<<Mrows, 128>>>(x, t1, ln1g, ln1b, x1, x1h, x1l);

    // mamba in-proj (mma, N=2048)
    gemm_mma<<<dim3(2*DINc/128, Mrows/128), 256>>>(x1h, x1l, Wih, Wil, nullptr,
                                                   xz, nullptr, nullptr, Dd, 2*DINc, Dd);

    // conv + silu
    conv_silu_k<<<(Mrows*DINc)/256, 256>>>(xz, cw, cb, xc);
    // dbl = xc @ Wx   (N=64, K=1024)
    gemm64<<<dim3(1, Mrows/64), 256>>>(xc, DINc, Wx, 64, nullptr, db, 64, DINc, 0);
    // dt = softplus(dbl[:, :32] @ Wdt + bdt)
    gemm64<<<dim3(DINc/64, Mrows/64), 256>>>(db, 64, Wdt, DINc, bdt, dtb, DINc, Rr, 1);
    // selective scan -> ya bf16 pair
    scan_k<<<Bb*(DINc/8), 128>>>(dtb, xc, db, xz, Alog, Dp, yah, yal);

    // out-proj (mma, K=1024) + final LN
    gemm_mma<<<dim3(Dd/128, Mrows/128), 256>>>(yah, yal, Wuh, Wul, nullptr,
                                               y, nullptr, nullptr, DINc, Dd, DINc);
    add_ln<<<Mrows, 128>>>(x1, y, ln2g, ln2b, out, nullptr, nullptr);

    (void)in_sizes; (void)n_in; (void)out_size;
}

// round 14
// speedup vs baseline: 1.6462x; 1.6462x over previous
#include <cuda_runtime.h>
#include <cuda_bf16.h>
#include <math.h>

// ---------------- problem constants ----------------
#define Bb   4
#define Ll   1024
#define Dd   512
#define Hh   8
#define Ee   64
#define DINc 1024
#define Nn   16
#define Rr   32
#define Mrows (Bb*Ll)          // 4096
#define QLD  1536              // fused qkv row stride

// ---------------- fp32 scratch ----------------
__device__ float g_t1[Mrows*Dd];
__device__ float g_x1[Mrows*Dd];
__device__ float g_xz[(size_t)Mrows*2*DINc];
__device__ float g_xc[(size_t)Mrows*DINc];
__device__ float g_db[Mrows*64];
__device__ float g_dt[(size_t)Mrows*DINc];
__device__ float g_y [Mrows*Dd];
__device__ float g_bqkv[3*Dd];

// ---------------- bf16 pair scratch (hi/lo) ----------------
__device__ __nv_bfloat16 g_xh [Mrows*Dd],   g_xl [Mrows*Dd];
__device__ __nv_bfloat16 g_qkvh[(size_t)Mrows*QLD], g_qkvl[(size_t)Mrows*QLD];
__device__ __nv_bfloat16 g_vth[(size_t)Bb*Hh*Ee*Ll], g_vtl[(size_t)Bb*Hh*Ee*Ll];
__device__ __nv_bfloat16 g_ah [(size_t)Bb*Hh*Ll*Ll], g_al [(size_t)Bb*Hh*Ll*Ll];
__device__ __nv_bfloat16 g_oh [Mrows*Dd],   g_ol [Mrows*Dd];
__device__ __nv_bfloat16 g_x1h[Mrows*Dd],   g_x1l[Mrows*Dd];
__device__ __nv_bfloat16 g_yah[(size_t)Mrows*DINc], g_yal[(size_t)Mrows*DINc];
// transposed weights [N][K]
__device__ __nv_bfloat16 g_Wqkvh[(size_t)3*Dd*Dd], g_Wqkvl[(size_t)3*Dd*Dd];
__device__ __nv_bfloat16 g_Woh[Dd*Dd],  g_Wol[Dd*Dd];
__device__ __nv_bfloat16 g_Wih[(size_t)Dd*2*DINc], g_Wil[(size_t)Dd*2*DINc];
__device__ __nv_bfloat16 g_Wuh[(size_t)DINc*Dd],   g_Wul[(size_t)DINc*Dd];

// ---------------- helpers ----------------
__device__ __forceinline__ unsigned sptr(const void* p){
    unsigned a;
    asm("{ .reg .u64 t; cvta.to.shared.u64 t, %1; cvt.u32.u64 %0, t; }" : "=r"(a) : "l"(p));
    return a;
}
__device__ __forceinline__ void ldm_x4(unsigned* f, unsigned addr){
    asm volatile("ldmatrix.sync.aligned.m8n8.x4.shared.b16 {%0,%1,%2,%3}, [%4];"
        : "=r"(f[0]), "=r"(f[1]), "=r"(f[2]), "=r"(f[3]) : "r"(addr));
}
__device__ __forceinline__ void mma16816(float* d, const unsigned* a,
                                         unsigned b0, unsigned b1){
    asm volatile(
        "mma.sync.aligned.m16n8k16.row.col.f32.bf16.bf16.f32 "
        "{%0,%1,%2,%3}, {%4,%5,%6,%7}, {%8,%9}, {%0,%1,%2,%3};"
        : "+f"(d[0]), "+f"(d[1]), "+f"(d[2]), "+f"(d[3])
        : "r"(a[0]), "r"(a[1]), "r"(a[2]), "r"(a[3]), "r"(b0), "r"(b1));
}
__device__ __forceinline__ void split2(float v, __nv_bfloat16& h, __nv_bfloat16& l){
    h = __float2bfloat16(v);
    l = __float2bfloat16(v - __bfloat162float(h));
}

// ====== unified 3x-split tensor-core GEMM (single-buffered, BK=32) ========
// C[M,N] = (Ah+Al)[M,K] @ (Bh+Bl)^T. A row stride lda; B [N][K] stride K.
// Output pair (Ch/Cl) or fp32 (Cf), stride ldc.
__global__ __launch_bounds__(256) void gemm_mma(
    const __nv_bfloat16* __restrict__ Ah, const __nv_bfloat16* __restrict__ Al,
    const __nv_bfloat16* __restrict__ Bh, const __nv_bfloat16* __restrict__ Bl,
    const float* __restrict__ bias,
    float* __restrict__ Cf, __nv_bfloat16* __restrict__ Ch,
    __nv_bfloat16* __restrict__ Cl, int lda, int ldc, int K)
{
    __shared__ __nv_bfloat16 sAh[128][40], sAl[128][40];
    __shared__ __nv_bfloat16 sBh[128][40], sBl[128][40];
    const int tid = threadIdx.x;
    const int wid = tid >> 5, lane = tid & 31;
    const int row0 = blockIdx.y * 128, col0 = blockIdx.x * 128;
    const int wm = (wid & 3) * 32;
    const int wn = (wid >> 2) * 64;

    float acc[2][8][4];
#pragma unroll
    for (int i=0;i<2;i++)
#pragma unroll
        for (int j=0;j<8;j++)
#pragma unroll
            for (int t=0;t<4;t++) acc[i][j][t]=0.f;

    const int lr = lane & 15, lh = (lane >> 4) * 8;

    for (int k0 = 0; k0 < K; k0 += 32) {
#pragma unroll
        for (int s = 0; s < 2; s++) {
            const int idx = s * 256 + tid;
            const int r = idx >> 2, c = (idx & 3) * 8;
            const long goff = (long)(row0 + r) * lda + k0 + c;
            const long hoff = (long)(col0 + r) * K + k0 + c;
            *(uint4*)&sAh[r][c] = *(const uint4*)(Ah + goff);
            *(uint4*)&sAl[r][c] = *(const uint4*)(Al + goff);
            *(uint4*)&sBh[r][c] = *(const uint4*)(Bh + hoff);
            *(uint4*)&sBl[r][c] = *(const uint4*)(Bl + hoff);
        }
        __syncthreads();

#pragma unroll
        for (int kk = 0; kk < 32; kk += 16) {
            unsigned ahf[2][4], alf[2][4];
#pragma unroll
            for (int mi = 0; mi < 2; mi++) {
                ldm_x4(ahf[mi], sptr(&sAh[wm + mi*16 + lr][kk + lh]));
                ldm_x4(alf[mi], sptr(&sAl[wm + mi*16 + lr][kk + lh]));
            }
#pragma unroll
            for (int half = 0; half < 2; half++) {
                unsigned bh[4][2], bl[4][2];
#pragma unroll
                for (int p = 0; p < 2; p++) {
                    unsigned f[4];
                    ldm_x4(f, sptr(&sBh[wn + half*32 + p*16 + lr][kk + lh]));
                    bh[2*p+0][0]=f[0]; bh[2*p+0][1]=f[2];
                    bh[2*p+1][0]=f[1]; bh[2*p+1][1]=f[3];
                    ldm_x4(f, sptr(&sBl[wn + half*32 + p*16 + lr][kk + lh]));
                    bl[2*p+0][0]=f[0]; bl[2*p+0][1]=f[2];
                    bl[2*p+1][0]=f[1]; bl[2*p+1][1]=f[3];
                }
#pragma unroll
                for (int mi = 0; mi < 2; mi++)
#pragma unroll
                    for (int nj = 0; nj < 4; nj++) {
                        float* a = acc[mi][half*4 + nj];
                        mma16816(a, ahf[mi], bh[nj][0], bh[nj][1]);
                        mma16816(a, ahf[mi], bl[nj][0], bl[nj][1]);
                        mma16816(a, alf[mi], bh[nj][0], bh[nj][1]);
                    }
            }
        }
        __syncthreads();
    }

#pragma unroll
    for (int mi = 0; mi < 2; mi++) {
        const int r = row0 + wm + mi*16 + (lane >> 2);
#pragma unroll
        for (int ni = 0; ni < 8; ni++) {
            const int c = col0 + wn + (ni>>2)*32 + (ni&3)*8 + (lane & 3)*2;
            float b0 = 0.f, b1 = 0.f;
            if (bias) { b0 = bias[c]; b1 = bias[c+1]; }
            const float v0 = acc[mi][ni][0]+b0, v1 = acc[mi][ni][1]+b1;
            const float v2 = acc[mi][ni][2]+b0, v3 = acc[mi][ni][3]+b1;
            if (Ch) {
                __nv_bfloat162 h2, l2;
                split2(v0, h2.x, l2.x); split2(v1, h2.y, l2.y);
                *(__nv_bfloat162*)(Ch + (long)r*ldc + c) = h2;
                *(__nv_bfloat162*)(Cl + (long)r*ldc + c) = l2;
                split2(v2, h2.x, l2.x); split2(v3, h2.y, l2.y);
                *(__nv_bfloat162*)(Ch + (long)(r+8)*ldc + c) = h2;
                *(__nv_bfloat162*)(Cl + (long)(r+8)*ldc + c) = l2;
            } else {
                *(float2*)(Cf + (long)r*ldc + c)     = make_float2(v0, v1);
                *(float2*)(Cf + (long)(r+8)*ldc + c) = make_float2(v2, v3);
            }
        }
    }
}

// ========== scores via mma (single-buffered): S = q @ k^T * 0.125 ==========
// q,k in fused qkv pair buffer, row stride QLD; k at col offset Dd.
__global__ __launch_bounds__(256) void scores_mma(
    const __nv_bfloat16* __restrict__ qkvh, const __nv_bfloat16* __restrict__ qkvl,
    float* __restrict__ attn)
{
    __shared__ __nv_bfloat16 sAh[128][40], sAl[128][40];
    __shared__ __nv_bfloat16 sBh[128][40], sBl[128][40];
    const int tid = threadIdx.x;
    const int wid = tid >> 5, lane = tid & 31;
    const int bz = blockIdx.z;
    const long abase = (long)(bz>>3)*Ll*QLD + (bz&7)*Ee;
    const long bbase = abase + Dd;
    float* C = attn + (long)bz*Ll*Ll;
    const int row0 = blockIdx.y * 128, col0 = blockIdx.x * 128;
    const int wm = (wid & 3) * 32;
    const int wn = (wid >> 2) * 64;

    float acc[2][8][4];
#pragma unroll
    for (int i=0;i<2;i++)
#pragma unroll
        for (int j=0;j<8;j++)
#pragma unroll
            for (int t=0;t<4;t++) acc[i][j][t]=0.f;

    const int lr = lane & 15, lh = (lane >> 4) * 8;

    for (int k0 = 0; k0 < Ee; k0 += 32) {
#pragma unroll
        for (int s = 0; s < 2; s++) {
            const int idx = s * 256 + tid;
            const int r = idx >> 2, c = (idx & 3) * 8;
            *(uint4*)&sAh[r][c] = *(const uint4*)(qkvh + abase + (long)(row0+r)*QLD + k0 + c);
            *(uint4*)&sAl[r][c] = *(const uint4*)(qkvl + abase + (long)(row0+r)*QLD + k0 + c);
            *(uint4*)&sBh[r][c] = *(const uint4*)(qkvh + bbase + (long)(col0+r)*QLD + k0 + c);
            *(uint4*)&sBl[r][c] = *(const uint4*)(qkvl + bbase + (long)(col0+r)*QLD + k0 + c);
        }
        __syncthreads();

#pragma unroll
        for (int kk = 0; kk < 32; kk += 16) {
            unsigned ahf[2][4], alf[2][4];
#pragma unroll
            for (int mi = 0; mi < 2; mi++) {
                ldm_x4(ahf[mi], sptr(&sAh[wm + mi*16 + lr][kk + lh]));
                ldm_x4(alf[mi], sptr(&sAl[wm + mi*16 + lr][kk + lh]));
            }
#pragma unroll
            for (int half = 0; half < 2; half++) {
                unsigned bh[4][2], bl[4][2];
#pragma unroll
                for (int p = 0; p < 2; p++) {
                    unsigned f[4];
                    ldm_x4(f, sptr(&sBh[wn + half*32 + p*16 + lr][kk + lh]));
                    bh[2*p+0][0]=f[0]; bh[2*p+0][1]=f[2];
                    bh[2*p+1][0]=f[1]; bh[2*p+1][1]=f[3];
                    ldm_x4(f, sptr(&sBl[wn + half*32 + p*16 + lr][kk + lh]));
                    bl[2*p+0][0]=f[0]; bl[2*p+0][1]=f[2];
                    bl[2*p+1][0]=f[1]; bl[2*p+1][1]=f[3];
                }
#pragma unroll
                for (int mi = 0; mi < 2; mi++)
#pragma unroll
                    for (int nj = 0; nj < 4; nj++) {
                        float* a = acc[mi][half*4 + nj];
                        mma16816(a, ahf[mi], bh[nj][0], bh[nj][1]);
                        mma16816(a, ahf[mi], bl[nj][0], bl[nj][1]);
                        mma16816(a, alf[mi], bh[nj][0], bh[nj][1]);
                    }
            }
        }
        __syncthreads();
    }

#pragma unroll
    for (int mi = 0; mi < 2; mi++) {
        const int r = row0 + wm + mi*16 + (lane >> 2);
#pragma unroll
        for (int ni = 0; ni < 8; ni++) {
            const int c = col0 + wn + (ni>>2)*32 + (ni&3)*8 + (lane & 3)*2;
            *(float2*)(C + (long)r*Ll + c) =
                make_float2(acc[mi][ni][0]*0.125f, acc[mi][ni][1]*0.125f);
            *(float2*)(C + (long)(r+8)*Ll + c) =
                make_float2(acc[mi][ni][2]*0.125f, acc[mi][ni][3]*0.125f);
        }
    }
}

// ====== attn @ v via mma (single-buffered): per (b,h), BM=128, BN=64 =======
__global__ __launch_bounds__(256) void attnv_mma(
    const __nv_bfloat16* __restrict__ ah, const __nv_bfloat16* __restrict__ al,
    const __nv_bfloat16* __restrict__ vth, const __nv_bfloat16* __restrict__ vtl,
    __nv_bfloat16* __restrict__ oh, __nv_bfloat16* __restrict__ ol)
{
    __shared__ __nv_bfloat16 sAh[128][40], sAl[128][40];
    __shared__ __nv_bfloat16 sBh[64][40],  sBl[64][40];
    const int tid = threadIdx.x;
    const int wid = tid >> 5, lane = tid & 31;
    const int bz = blockIdx.z;
    const __nv_bfloat16* Abh = ah + (long)bz*Ll*Ll;
    const __nv_bfloat16* Abl = al + (long)bz*Ll*Ll;
    const __nv_bfloat16* Bbh = vth + (long)bz*Ee*Ll;
    const __nv_bfloat16* Bbl = vtl + (long)bz*Ee*Ll;
    const long obase = (long)(bz>>3)*Ll*Dd + (bz&7)*Ee;
    const int row0 = blockIdx.y * 128;
    const int wm = (wid & 3) * 32;
    const int wn = (wid >> 2) * 32;

    float acc[2][4][4];
#pragma unroll
    for (int i=0;i<2;i++)
#pragma unroll
        for (int j=0;j<4;j++)
#pragma unroll
            for (int t=0;t<4;t++) acc[i][j][t]=0.f;

    const int lr = lane & 15, lh = (lane >> 4) * 8;

    for (int k0 = 0; k0 < Ll; k0 += 32) {
#pragma unroll
        for (int s = 0; s < 2; s++) {
            const int idx = s * 256 + tid;
            const int r = idx >> 2, c = (idx & 3) * 8;
            *(uint4*)&sAh[r][c] = *(const uint4*)(Abh + (long)(row0+r)*Ll + k0 + c);
            *(uint4*)&sAl[r][c] = *(const uint4*)(Abl + (long)(row0+r)*Ll + k0 + c);
        }
        {
            const int r = tid >> 2, c = (tid & 3) * 8;
            *(uint4*)&sBh[r][c] = *(const uint4*)(Bbh + (long)r*Ll + k0 + c);
            *(uint4*)&sBl[r][c] = *(const uint4*)(Bbl + (long)r*Ll + k0 + c);
        }
        __syncthreads();

#pragma unroll
        for (int kk = 0; kk < 32; kk += 16) {
            unsigned ahf[2][4], alf[2][4];
#pragma unroll
            for (int mi = 0; mi < 2; mi++) {
                ldm_x4(ahf[mi], sptr(&sAh[wm + mi*16 + lr][kk + lh]));
                ldm_x4(alf[mi], sptr(&sAl[wm + mi*16 + lr][kk + lh]));
            }
            unsigned bh[4][2], bl[4][2];
#pragma unroll
            for (int p = 0; p < 2; p++) {
                unsigned f[4];
                ldm_x4(f, sptr(&sBh[wn + p*16 + lr][kk + lh]));
                bh[2*p+0][0]=f[0]; bh[2*p+0][1]=f[2];
                bh[2*p+1][0]=f[1]; bh[2*p+1][1]=f[3];
                ldm_x4(f, sptr(&sBl[wn + p*16 + lr][kk + lh]));
                bl[2*p+0][0]=f[0]; bl[2*p+0][1]=f[2];
                bl[2*p+1][0]=f[1]; bl[2*p+1][1]=f[3];
            }
#pragma unroll
            for (int mi = 0; mi < 2; mi++)
#pragma unroll
                for (int nj = 0; nj < 4; nj++) {
                    float* a = acc[mi][nj];
                    mma16816(a, ahf[mi], bh[nj][0], bh[nj][1]);
                    mma16816(a, ahf[mi], bl[nj][0], bl[nj][1]);
                    mma16816(a, alf[mi], bh[nj][0], bh[nj][1]);
                }
        }
        __syncthreads();
    }

#pragma unroll
    for (int mi = 0; mi < 2; mi++) {
        const int r = row0 + wm + mi*16 + (lane >> 2);
#pragma unroll
        for (int nj = 0; nj < 4; nj++) {
            const int c = wn + nj*8 + (lane & 3)*2;
            __nv_bfloat162 h2, l2;
            split2(acc[mi][nj][0], h2.x, l2.x);
            split2(acc[mi][nj][1], h2.y, l2.y);
            *(__nv_bfloat162*)(oh + obase + (long)r*Dd + c) = h2;
            *(__nv_bfloat162*)(ol + obase + (long)r*Dd + c) = l2;
            split2(acc[mi][nj][2], h2.x, l2.x);
            split2(acc[mi][nj][3], h2.y, l2.y);
            *(__nv_bfloat162*)(oh + obase + (long)(r+8)*Dd + c) = h2;
            *(__nv_bfloat162*)(ol + obase + (long)(r+8)*Dd + c) = l2;
        }
    }
}

// ================= split conversions =======================================
__global__ __launch_bounds__(256) void split_act(
    const float* __restrict__ x, __nv_bfloat16* __restrict__ h,
    __nv_bfloat16* __restrict__ l)
{
    const int i = blockIdx.x * 256 + threadIdx.x;
    const float v = x[i];
    __nv_bfloat16 hi, lo; split2(v, hi, lo);
    h[i] = hi; l[i] = lo;
}

// W [K][N] fp32 -> Wt hi/lo bf16 [N][K]
__global__ __launch_bounds__(256) void split_wt(
    const float* __restrict__ W, int Kdim, int Ndim,
    __nv_bfloat16* __restrict__ h, __nv_bfloat16* __restrict__ l)
{
    __shared__ float t[32][33];
    const int tx = threadIdx.x, ty = threadIdx.y;
    const int n0 = blockIdx.x * 32, k0 = blockIdx.y * 32;
#pragma unroll
    for (int j = 0; j < 4; j++)
        t[ty + 8 * j][tx] = W[(long)(k0 + ty + 8 * j) * Ndim + n0 + tx];
    __syncthreads();
#pragma unroll
    for (int j = 0; j < 4; j++) {
        const float v = t[tx][ty + 8 * j];
        __nv_bfloat16 hi, lo; split2(v, hi, lo);
        const long oidx = (long)(n0 + ty + 8 * j) * Kdim + k0 + tx;
        h[oidx] = hi; l[oidx] = lo;
    }
}

// v (in fused qkv pair, col offset 2*Dd, row stride QLD) -> vT pair [bh][e][s]
__global__ void vtrans(
    const __nv_bfloat16* __restrict__ qkvh, const __nv_bfloat16* __restrict__ qkvl,
    __nv_bfloat16* __restrict__ vth, __nv_bfloat16* __restrict__ vtl)
{
    __shared__ __nv_bfloat16 th[32][33], tl[32][33];
    const int tx = threadIdx.x, ty = threadIdx.y;   // (32, 8)
    const int bh = blockIdx.z;
    const int b = bh >> 3, h = bh & 7;
    const int s0 = blockIdx.x * 32, e0 = blockIdx.y * 32;
    const long ibase = (long)b*Ll*QLD + 2*Dd + h*Ee;
#pragma unroll
    for (int j = 0; j < 4; j++) {
        const long off = ibase + (long)(s0 + ty + 8*j)*QLD + e0 + tx;
        th[ty+8*j][tx] = qkvh[off];
        tl[ty+8*j][tx] = qkvl[off];
    }
    __syncthreads();
    const long obase = (long)bh*Ee*Ll;
#pragma unroll
    for (int j = 0; j < 4; j++) {
        const long off = obase + (long)(e0 + ty + 8*j)*Ll + s0 + tx;
        vth[off] = th[tx][ty+8*j];
        vtl[off] = tl[tx][ty+8*j];
    }
}

// ------- softmax rows of 1024 (float4 I/O), in place + bf16 pair output ----
__global__ __launch_bounds__(256) void softmax_split(
    float* __restrict__ a, __nv_bfloat16* __restrict__ ah,
    __nv_bfloat16* __restrict__ al)
{
    const long row = blockIdx.x;
    float* p = a + row * (long)Ll;
    __nv_bfloat16* ph = ah + row * (long)Ll;
    __nv_bfloat16* pl = al + row * (long)Ll;
    const int tid = threadIdx.x;

    float4 v4 = *(float4*)(p + tid * 4);
    float m = fmaxf(fmaxf(v4.x, v4.y), fmaxf(v4.z, v4.w));
#pragma unroll
    for (int off=16; off; off>>=1) m = fmaxf(m, __shfl_xor_sync(0xffffffffu, m, off));
    __shared__ float sm[8], ss[8];
    const int w = tid >> 5, lane = tid & 31;
    if (lane==0) sm[w] = m;
    __syncthreads();
    m = sm[0];
#pragma unroll
    for (int i=1;i<8;i++) m = fmaxf(m, sm[i]);
    v4.x = __expf(v4.x - m); v4.y = __expf(v4.y - m);
    v4.z = __expf(v4.z - m); v4.w = __expf(v4.w - m);
    float s = v4.x + v4.y + v4.z + v4.w;
#pragma unroll
    for (int off=16; off; off>>=1) s += __shfl_xor_sync(0xffffffffu, s, off);
    if (lane==0) ss[w] = s;
    __syncthreads();
    s = 0.f;
#pragma unroll
    for (int i=0;i<8;i++) s += ss[i];
    const float inv = 1.f / s;
    v4.x *= inv; v4.y *= inv; v4.z *= inv; v4.w *= inv;
    *(float4*)(p + tid * 4) = v4;
    __nv_bfloat162 h01, l01, h23, l23;
    split2(v4.x, h01.x, l01.x); split2(v4.y, h01.y, l01.y);
    split2(v4.z, h23.x, l23.x); split2(v4.w, h23.y, l23.y);
    *(__nv_bfloat162*)(ph + tid*4)     = h01;
    *(__nv_bfloat162*)(ph + tid*4 + 2) = h23;
    *(__nv_bfloat162*)(pl + tid*4)     = l01;
    *(__nv_bfloat162*)(pl + tid*4 + 2) = l23;
}

// ---------------- out = LayerNorm(xa + xb) (+ optional bf16 pair) ----------
__global__ __launch_bounds__(128) void add_ln(
    const float* __restrict__ xa, const float* __restrict__ xb,
    const float* __restrict__ g, const float* __restrict__ bt,
    float* __restrict__ out, __nv_bfloat16* __restrict__ oh,
    __nv_bfloat16* __restrict__ ol)
{
    const int row = blockIdx.x, tid = threadIdx.x;
    const float* pa = xa + (long)row*Dd;
    const float* pb = xb + (long)row*Dd;
    float v[4]; float s1=0.f, s2=0.f;
#pragma unroll
    for (int i=0;i<4;i++){ int c = tid + 128*i; v[i] = pa[c] + pb[c]; s1 += v[i]; s2 += v[i]*v[i]; }
#pragma unroll
    for (int off=16; off; off>>=1){
        s1 += __shfl_xor_sync(0xffffffffu, s1, off);
        s2 += __shfl_xor_sync(0xffffffffu, s2, off);
    }
    __shared__ float r1[4], r2[4];
    const int w = tid >> 5, lane = tid & 31;
    if (lane==0){ r1[w]=s1; r2[w]=s2; }
    __syncthreads();
    s1 = r1[0]+r1[1]+r1[2]+r1[3];
    s2 = r2[0]+r2[1]+r2[2]+r2[3];
    const float mean = s1 * (1.f/Dd);
    const float var  = s2 * (1.f/Dd) - mean*mean;
    const float rstd = rsqrtf(var + 1e-5f);
    float* po = out + (long)row*Dd;
#pragma unroll
    for (int i=0;i<4;i++){
        const int c = tid + 128*i;
        const float val = (v[i]-mean)*rstd*g[c] + bt[c];
        po[c] = val;
        if (oh) {
            __nv_bfloat16 hi, lo; split2(val, hi, lo);
            oh[(long)row*Dd + c] = hi;
            ol[(long)row*Dd + c] = lo;
        }
    }
}

// ============ 64x64 GEMM for small N problems (Wx, Wdt) ====================
__global__ __launch_bounds__(256) void gemm64(
    const float* __restrict__ A, int lda,
    const float* __restrict__ W, int ldw,
    const float* __restrict__ bias,
    float* __restrict__ C, int ldc, int K, int act)
{
    __shared__ float As[16][64];
    __shared__ float Ws[16][68];
    const int tid = threadIdx.x;
    const int row0 = blockIdx.y * 64;
    const int col0 = blockIdx.x * 64;
    const int ar = tid >> 2, ac = (tid & 3) * 4;
    const int br = tid >> 4, bc = (tid & 15) * 4;
    const int tm = (tid & 15) * 4, tn = (tid >> 4) * 4;
    float acc[4][4];
#pragma unroll
    for (int i=0;i<4;i++)
#pragma unroll
        for (int j=0;j<4;j++) acc[i][j]=0.f;

    for (int k0 = 0; k0 < K; k0 += 16) {
        float4 a4 = *(const float4*)(A + (long)(row0+ar)*lda + k0 + ac);
        As[ac+0][ar]=a4.x; As[ac+1][ar]=a4.y; As[ac+2][ar]=a4.z; As[ac+3][ar]=a4.w;
        float4 b4 = *(const float4*)(W + (long)(k0+br)*ldw + col0 + bc);
        *(float4*)&Ws[br][bc] = b4;
        __syncthreads();
#pragma unroll
        for (int k=0;k<16;k++){
            float a[4], b[4];
#pragma unroll
            for (int i=0;i<4;i++) a[i]=As[k][tm+i];
#pragma unroll
            for (int j=0;j<4;j++) b[j]=Ws[k][tn+j];
#pragma unroll
            for (int i=0;i<4;i++)
#pragma unroll
                for (int j=0;j<4;j++) acc[i][j]=fmaf(a[i],b[j],acc[i][j]);
        }
        __syncthreads();
    }
#pragma unroll
    for (int j=0;j<4;j++){
        int c = col0 + tn + j;
        float bvv = bias ? bias[c] : 0.f;
#pragma unroll
        for (int i=0;i<4;i++){
            float vv = acc[i][j] + bvv;
            if (act == 1) vv = (vv > 20.f) ? vv : log1pf(__expf(vv));
            C[(long)(row0+tm+i)*ldc + c] = vv;
        }
    }
}

// ---------------- depthwise causal conv (K=4) + bias + silu ----------------
__global__ __launch_bounds__(256) void conv_silu_k(
    const float* __restrict__ xz, const float* __restrict__ w,
    const float* __restrict__ cb, float* __restrict__ xc)
{
    const long idx = (long)blockIdx.x*256 + threadIdx.x;
    const int d = (int)(idx & (DINc-1));
    const long row = idx >> 10;
    const int l = (int)(row & (Ll-1));
    float acc = cb[d];
#pragma unroll
    for (int j=0;j<4;j++) {
        int ll = l - 3 + j;
        if (ll >= 0)
            acc = fmaf(xz[(row-3+j)*(2*DINc) + d], w[d*4+j], acc);
    }
    xc[idx] = acc / (1.f + __expf(-acc));
}

// ---------- selective scan, depth-8 load pipeline, bf16 pair output --------
#define PFD 8
__global__ __launch_bounds__(128) void scan_k(
    const float* __restrict__ dt, const float* __restrict__ xc,
    const float* __restrict__ dbl, const float* __restrict__ xz,
    const float* __restrict__ Alog, const float* __restrict__ Dp,
    __nv_bfloat16* __restrict__ yh, __nv_bfloat16* __restrict__ yl)
{
    const int tid = threadIdx.x;
    const int n  = tid & 15;
    const int dl = tid >> 4;
    const int b  = blockIdx.x >> 7;
    const int d  = (blockIdx.x & 127)*8 + dl;
    const float Aa = -__expf(Alog[d*Nn + n]);
    const float Dv = Dp[d];
    float h = 0.f;
    const long base = (long)b * Ll;

    float rdt[PFD], rxc[PFD], rB[PFD], rC[PFD], rz[PFD];
#pragma unroll
    for (int i = 0; i < PFD; i++) {
        const long r = base + i;
        rdt[i] = dt[r*DINc + d];
        rxc[i] = xc[r*DINc + d];
        rB[i]  = dbl[r*64 + 32 + n];
        rC[i]  = dbl[r*64 + 48 + n];
        rz[i]  = xz[r*(2*DINc) + DINc + d];
    }

    for (int t0 = 0; t0 < Ll; t0 += PFD) {
        float ndt[PFD], nxc[PFD], nB[PFD], nC[PFD], nz[PFD];
        const bool more = (t0 + PFD) < Ll;
        if (more) {
#pragma unroll
            for (int i = 0; i < PFD; i++) {
                const long r = base + t0 + PFD + i;
                ndt[i] = dt[r*DINc + d];
                nxc[i] = xc[r*DINc + d];
                nB[i]  = dbl[r*64 + 32 + n];
                nC[i]  = dbl[r*64 + 48 + n];
                nz[i]  = xz[r*(2*DINc) + DINc + d];
            }
        }
#pragma unroll
        for (int i = 0; i < PFD; i++) {
            const float dA = __expf(rdt[i] * Aa);
            h = fmaf(h, dA, rdt[i] * rxc[i] * rB[i]);
            float p = h * rC[i];
            p += __shfl_xor_sync(0xffffffffu, p, 8);
            p += __shfl_xor_sync(0xffffffffu, p, 4);
            p += __shfl_xor_sync(0xffffffffu, p, 2);
            p += __shfl_xor_sync(0xffffffffu, p, 1);
            if (n == 0) {
                const float sz = rz[i] / (1.f + __expf(-rz[i]));
                const float val = (p + rxc[i] * Dv) * sz;
                __nv_bfloat16 hi, lo; split2(val, hi, lo);
                yh[(base + t0 + i)*DINc + d] = hi;
                yl[(base + t0 + i)*DINc + d] = lo;
            }
        }
        if (more) {
#pragma unroll
            for (int i = 0; i < PFD; i++) {
                rdt[i]=ndt[i]; rxc[i]=nxc[i]; rB[i]=nB[i]; rC[i]=nC[i]; rz[i]=nz[i];
            }
        }
    }
}

// ---------------- launch ----------------------------------------------------
extern "C" void kernel_launch(void* const* d_in, const int* in_sizes, int n_in,
                              void* d_out, int out_size)
{
    const float* x    = (const float*)d_in[0];
    const float* Wq   = (const float*)d_in[1];
    const float* bq   = (const float*)d_in[2];
    const float* Wk   = (const float*)d_in[3];
    const float* bk   = (const float*)d_in[4];
    const float* Wv   = (const float*)d_in[5];
    const float* bv   = (const float*)d_in[6];
    const float* Wo   = (const float*)d_in[7];
    const float* bo   = (const float*)d_in[8];
    const float* ln1g = (const float*)d_in[9];
    const float* ln1b = (const float*)d_in[10];
    const float* ln2g = (const float*)d_in[11];
    const float* ln2b = (const float*)d_in[12];
    const float* Win  = (const float*)d_in[13];
    const float* cw   = (const float*)d_in[14];
    const float* cb   = (const float*)d_in[15];
    const float* Wx   = (const float*)d_in[16];
    const float* Wdt  = (const float*)d_in[17];
    const float* bdt  = (const float*)d_in[18];
    const float* Alog = (const float*)d_in[19];
    const float* Dp   = (const float*)d_in[20];
    const float* Wout = (const float*)d_in[21];

    float* out  = (float*)d_out;
    float* attn = out + (size_t)Bb*Ll*Dd;

    float *t1,*x1,*xz,*xc,*db,*dtb,*y,*bqkv;
    cudaGetSymbolAddress((void**)&t1, g_t1);
    cudaGetSymbolAddress((void**)&x1, g_x1);
    cudaGetSymbolAddress((void**)&xz, g_xz);
    cudaGetSymbolAddress((void**)&xc, g_xc);
    cudaGetSymbolAddress((void**)&db, g_db);
    cudaGetSymbolAddress((void**)&dtb,g_dt);
    cudaGetSymbolAddress((void**)&y,  g_y);
    cudaGetSymbolAddress((void**)&bqkv, g_bqkv);

    __nv_bfloat16 *xh,*xl,*qkvh,*qkvl,*vth,*vtl,*ah,*al,*oh,*ol,*x1h,*x1l,*yah,*yal;
    __nv_bfloat16 *Wqkvh,*Wqkvl,*Woh,*Wol,*Wih,*Wil,*Wuh,*Wul;
    cudaGetSymbolAddress((void**)&xh,   g_xh);   cudaGetSymbolAddress((void**)&xl,   g_xl);
    cudaGetSymbolAddress((void**)&qkvh, g_qkvh); cudaGetSymbolAddress((void**)&qkvl, g_qkvl);
    cudaGetSymbolAddress((void**)&vth,  g_vth);  cudaGetSymbolAddress((void**)&vtl,  g_vtl);
    cudaGetSymbolAddress((void**)&ah,   g_ah);   cudaGetSymbolAddress((void**)&al,   g_al);
    cudaGetSymbolAddress((void**)&oh,   g_oh);   cudaGetSymbolAddress((void**)&ol,   g_ol);
    cudaGetSymbolAddress((void**)&x1h,  g_x1h);  cudaGetSymbolAddress((void**)&x1l,  g_x1l);
    cudaGetSymbolAddress((void**)&yah,  g_yah);  cudaGetSymbolAddress((void**)&yal,  g_yal);
    cudaGetSymbolAddress((void**)&Wqkvh,g_Wqkvh);cudaGetSymbolAddress((void**)&Wqkvl,g_Wqkvl);
    cudaGetSymbolAddress((void**)&Woh,  g_Woh);  cudaGetSymbolAddress((void**)&Wol,  g_Wol);
    cudaGetSymbolAddress((void**)&Wih,  g_Wih);  cudaGetSymbolAddress((void**)&Wil,  g_Wil);
    cudaGetSymbolAddress((void**)&Wuh,  g_Wuh);  cudaGetSymbolAddress((void**)&Wul,  g_Wul);

    // weight conversions (transpose + hi/lo split); qkv fused [1536][512]
    split_wt<<<dim3(Dd/32, Dd/32), dim3(32,8)>>>(Wq, Dd, Dd, Wqkvh,            Wqkvl);
    split_wt<<<dim3(Dd/32, Dd/32), dim3(32,8)>>>(Wk, Dd, Dd, Wqkvh + Dd*Dd,    Wqkvl + Dd*Dd);
    split_wt<<<dim3(Dd/32, Dd/32), dim3(32,8)>>>(Wv, Dd, Dd, Wqkvh + 2*Dd*Dd,  Wqkvl + 2*Dd*Dd);
    split_wt<<<dim3(Dd/32, Dd/32), dim3(32,8)>>>(Wo, Dd, Dd, Woh, Wol);
    split_wt<<<dim3(2*DINc/32, Dd/32), dim3(32,8)>>>(Win, Dd, 2*DINc, Wih, Wil);
    split_wt<<<dim3(Dd/32, DINc/32), dim3(32,8)>>>(Wout, DINc, Dd, Wuh, Wul);
    cudaMemcpyAsync(bqkv,        bq, Dd*sizeof(float), cudaMemcpyDeviceToDevice, 0);
    cudaMemcpyAsync(bqkv + Dd,   bk, Dd*sizeof(float), cudaMemcpyDeviceToDevice, 0);
    cudaMemcpyAsync(bqkv + 2*Dd, bv, Dd*sizeof(float), cudaMemcpyDeviceToDevice, 0);

    // x split + fused QKV (mma, pair output, ldc=1536)
    split_act<<<(Mrows*Dd)/256, 256>>>(x, xh, xl);
    gemm_mma<<<dim3(QLD/128, Mrows/128), 256>>>(xh, xl, Wqkvh, Wqkvl, bqkv,
                                                nullptr, qkvh, qkvl, Dd, QLD, Dd);
    vtrans<<<dim3(Ll/32, Ee/32, Bb*Hh), dim3(32,8)>>>(qkvh, qkvl, vth, vtl);

    // attention
    scores_mma<<<dim3(Ll/128, Ll/128, Bb*Hh), 256>>>(qkvh, qkvl, attn);
    softmax_split<<<Bb*Hh*Ll, 256>>>(attn, ah, al);
    attnv_mma<<<dim3(1, Ll/128, Bb*Hh), 256>>>(ah, al, vth, vtl, oh, ol);

    // o @ Wo + bo (mma) ; x1 = LN(x + .) with pair output
    gemm_mma<<<dim3(Dd/128, Mrows/128), 256>>>(oh, ol, Woh, Wol, bo,
                                               t1, nullptr, nullptr, Dd, Dd, Dd);
    add_ln<<<Mrows, 128>>>(x, t1, ln1g, ln1b, x1, x1h, x1l);

    // mamba in-proj (mma, N=2048)
    gemm_mma<<<dim3(2*DINc/128, Mrows/128), 256>>>(x1h, x1l, Wih, Wil, nullptr,
                                                   xz, nullptr, nullptr, Dd, 2*DINc, Dd);

    // conv + silu
    conv_silu_k<<<(Mrows*DINc)/256, 256>>>(xz, cw, cb, xc);
    // dbl = xc @ Wx   (N=64, K=1024)
    gemm64<<<dim3(1, Mrows/64), 256>>>(xc, DINc, Wx, 64, nullptr, db, 64, DINc, 0);
    // dt = softplus(dbl[:, :32] @ Wdt + bdt)
    gemm64<<<dim3(DINc/64, Mrows/64), 256>>>(db, 64, Wdt, DINc, bdt, dtb, DINc, Rr, 1);
    // selective scan -> ya bf16 pair
    scan_k<<<Bb*(DINc/8), 128>>>(dtb, xc, db, xz, Alog, Dp, yah, yal);

    // out-proj (mma, K=1024) + final LN
    gemm_mma<<<dim3(Dd/128, Mrows/128), 256>>>(yah, yal, Wuh, Wul, nullptr,
                                               y, nullptr, nullptr, DINc, Dd, DINc);
    add_ln<<<Mrows, 128>>>(x1, y, ln2g, ln2b, out, nullptr, nullptr);

    (void)in_sizes; (void)n_in; (void)out_size;
}

// round 15
// speedup vs baseline: 1.6933x; 1.0286x over previous
#include <cuda_runtime.h>
#include <cuda_bf16.h>
#include <math.h>

// ---------------- problem constants ----------------
#define Bb   4
#define Ll   1024
#define Dd   512
#define Hh   8
#define Ee   64
#define DINc 1024
#define Nn   16
#define Rr   32
#define Mrows (Bb*Ll)          // 4096

// ---------------- fp32 scratch ----------------
__device__ float g_t1[Mrows*Dd];
__device__ float g_x1[Mrows*Dd];
__device__ float g_xz[(size_t)Mrows*2*DINc];
__device__ float g_xc[(size_t)Mrows*DINc];
__device__ float g_db[Mrows*64];
__device__ float g_dt[(size_t)Mrows*DINc];
__device__ float g_y [Mrows*Dd];

// ---------------- bf16 pair scratch (hi/lo) ----------------
__device__ __nv_bfloat16 g_xh [Mrows*Dd],   g_xl [Mrows*Dd];
__device__ __nv_bfloat16 g_qh [Mrows*Dd],   g_ql [Mrows*Dd];
__device__ __nv_bfloat16 g_kh [Mrows*Dd],   g_kl [Mrows*Dd];
__device__ __nv_bfloat16 g_vh [Mrows*Dd],   g_vl [Mrows*Dd];
__device__ __nv_bfloat16 g_vth[(size_t)Bb*Hh*Ee*Ll], g_vtl[(size_t)Bb*Hh*Ee*Ll];
__device__ __nv_bfloat16 g_ah [(size_t)Bb*Hh*Ll*Ll], g_al [(size_t)Bb*Hh*Ll*Ll];
__device__ __nv_bfloat16 g_oh [Mrows*Dd],   g_ol [Mrows*Dd];
__device__ __nv_bfloat16 g_x1h[Mrows*Dd],   g_x1l[Mrows*Dd];
__device__ __nv_bfloat16 g_yah[(size_t)Mrows*DINc], g_yal[(size_t)Mrows*DINc];
// transposed weights [N][K]
__device__ __nv_bfloat16 g_Wqh[Dd*Dd],  g_Wql[Dd*Dd];
__device__ __nv_bfloat16 g_Wkh[Dd*Dd],  g_Wkl[Dd*Dd];
__device__ __nv_bfloat16 g_Wvh[Dd*Dd],  g_Wvl[Dd*Dd];
__device__ __nv_bfloat16 g_Woh[Dd*Dd],  g_Wol[Dd*Dd];
__device__ __nv_bfloat16 g_Wih[(size_t)Dd*2*DINc], g_Wil[(size_t)Dd*2*DINc];
__device__ __nv_bfloat16 g_Wuh[(size_t)DINc*Dd],   g_Wul[(size_t)DINc*Dd];

// ---------------- helpers ----------------
__device__ __forceinline__ unsigned sptr(const void* p){
    unsigned a;
    asm("{ .reg .u64 t; cvta.to.shared.u64 t, %1; cvt.u32.u64 %0, t; }" : "=r"(a) : "l"(p));
    return a;
}
__device__ __forceinline__ void ldm_x4(unsigned* f, unsigned addr){
    asm volatile("ldmatrix.sync.aligned.m8n8.x4.shared.b16 {%0,%1,%2,%3}, [%4];"
        : "=r"(f[0]), "=r"(f[1]), "=r"(f[2]), "=r"(f[3]) : "r"(addr));
}
__device__ __forceinline__ void mma16816(float* d, const unsigned* a,
                                         unsigned b0, unsigned b1){
    asm volatile(
        "mma.sync.aligned.m16n8k16.row.col.f32.bf16.bf16.f32 "
        "{%0,%1,%2,%3}, {%4,%5,%6,%7}, {%8,%9}, {%0,%1,%2,%3};"
        : "+f"(d[0]), "+f"(d[1]), "+f"(d[2]), "+f"(d[3])
        : "r"(a[0]), "r"(a[1]), "r"(a[2]), "r"(a[3]), "r"(b0), "r"(b1));
}
__device__ __forceinline__ void split2(float v, __nv_bfloat16& h, __nv_bfloat16& l){
    h = __float2bfloat16(v);
    l = __float2bfloat16(v - __bfloat162float(h));
}

// ================= unified 3x-split tensor-core GEMM =======================
// C[M,N] = (Ah+Al)[M,K] @ (Bh+Bl)^T, B stored [N][K]. BM=BN=128, BK=32.
// Output: if Ch != nullptr, write bf16 hi/lo pair; else fp32 to Cf.
__global__ __launch_bounds__(256) void gemm_mma(
    const __nv_bfloat16* __restrict__ Ah, const __nv_bfloat16* __restrict__ Al,
    const __nv_bfloat16* __restrict__ Bh, const __nv_bfloat16* __restrict__ Bl,
    const float* __restrict__ bias,
    float* __restrict__ Cf, __nv_bfloat16* __restrict__ Ch,
    __nv_bfloat16* __restrict__ Cl, int ldc, int K)
{
    __shared__ __nv_bfloat16 sAh[128][40], sAl[128][40];
    __shared__ __nv_bfloat16 sBh[128][40], sBl[128][40];
    const int tid = threadIdx.x;
    const int wid = tid >> 5, lane = tid & 31;
    const int row0 = blockIdx.y * 128, col0 = blockIdx.x * 128;
    const int wm = (wid & 3) * 32;
    const int wn = (wid >> 2) * 64;

    float acc[2][8][4];
#pragma unroll
    for (int i=0;i<2;i++)
#pragma unroll
        for (int j=0;j<8;j++)
#pragma unroll
            for (int t=0;t<4;t++) acc[i][j][t]=0.f;

    const int lr = lane & 15, lh = (lane >> 4) * 8;

    for (int k0 = 0; k0 < K; k0 += 32) {
#pragma unroll
        for (int s = 0; s < 2; s++) {
            const int idx = s * 256 + tid;
            const int r = idx >> 2, c = (idx & 3) * 8;
            const long goff = (long)(row0 + r) * K + k0 + c;
            const long hoff = (long)(col0 + r) * K + k0 + c;
            *(uint4*)&sAh[r][c] = *(const uint4*)(Ah + goff);
            *(uint4*)&sAl[r][c] = *(const uint4*)(Al + goff);
            *(uint4*)&sBh[r][c] = *(const uint4*)(Bh + hoff);
            *(uint4*)&sBl[r][c] = *(const uint4*)(Bl + hoff);
        }
        __syncthreads();

#pragma unroll
        for (int kk = 0; kk < 32; kk += 16) {
            unsigned ahf[2][4], alf[2][4];
#pragma unroll
            for (int mi = 0; mi < 2; mi++) {
                ldm_x4(ahf[mi], sptr(&sAh[wm + mi*16 + lr][kk + lh]));
                ldm_x4(alf[mi], sptr(&sAl[wm + mi*16 + lr][kk + lh]));
            }
#pragma unroll
            for (int half = 0; half < 2; half++) {
                unsigned bh[4][2], bl[4][2];
#pragma unroll
                for (int p = 0; p < 2; p++) {
                    unsigned f[4];
                    ldm_x4(f, sptr(&sBh[wn + half*32 + p*16 + lr][kk + lh]));
                    bh[2*p+0][0]=f[0]; bh[2*p+0][1]=f[2];
                    bh[2*p+1][0]=f[1]; bh[2*p+1][1]=f[3];
                    ldm_x4(f, sptr(&sBl[wn + half*32 + p*16 + lr][kk + lh]));
                    bl[2*p+0][0]=f[0]; bl[2*p+0][1]=f[2];
                    bl[2*p+1][0]=f[1]; bl[2*p+1][1]=f[3];
                }
#pragma unroll
                for (int mi = 0; mi < 2; mi++)
#pragma unroll
                    for (int nj = 0; nj < 4; nj++) {
                        float* a = acc[mi][half*4 + nj];
                        mma16816(a, ahf[mi], bh[nj][0], bh[nj][1]);
                        mma16816(a, ahf[mi], bl[nj][0], bl[nj][1]);
                        mma16816(a, alf[mi], bh[nj][0], bh[nj][1]);
                    }
            }
        }
        __syncthreads();
    }

#pragma unroll
    for (int mi = 0; mi < 2; mi++) {
        const int r = row0 + wm + mi*16 + (lane >> 2);
#pragma unroll
        for (int ni = 0; ni < 8; ni++) {
            const int c = col0 + wn + (ni>>2)*32 + (ni&3)*8 + (lane & 3)*2;
            float b0 = 0.f, b1 = 0.f;
            if (bias) { b0 = bias[c]; b1 = bias[c+1]; }
            const float v0 = acc[mi][ni][0]+b0, v1 = acc[mi][ni][1]+b1;
            const float v2 = acc[mi][ni][2]+b0, v3 = acc[mi][ni][3]+b1;
            if (Ch) {
                __nv_bfloat162 h2, l2;
                split2(v0, h2.x, l2.x); split2(v1, h2.y, l2.y);
                *(__nv_bfloat162*)(Ch + (long)r*ldc + c) = h2;
                *(__nv_bfloat162*)(Cl + (long)r*ldc + c) = l2;
                split2(v2, h2.x, l2.x); split2(v3, h2.y, l2.y);
                *(__nv_bfloat162*)(Ch + (long)(r+8)*ldc + c) = h2;
                *(__nv_bfloat162*)(Cl + (long)(r+8)*ldc + c) = l2;
            } else {
                *(float2*)(Cf + (long)r*ldc + c)     = make_float2(v0, v1);
                *(float2*)(Cf + (long)(r+8)*ldc + c) = make_float2(v2, v3);
            }
        }
    }
}

// ================= scores via mma: S = q @ k^T * 0.125 =====================
__global__ __launch_bounds__(256) void scores_mma(
    const __nv_bfloat16* __restrict__ qh, const __nv_bfloat16* __restrict__ ql,
    const __nv_bfloat16* __restrict__ kh, const __nv_bfloat16* __restrict__ kl,
    float* __restrict__ attn)
{
    __shared__ __nv_bfloat16 sAh[128][40], sAl[128][40];
    __shared__ __nv_bfloat16 sBh[128][40], sBl[128][40];
    const int tid = threadIdx.x;
    const int wid = tid >> 5, lane = tid & 31;
    const int bz = blockIdx.z;
    const long abase = (long)(bz>>3)*Ll*Dd + (bz&7)*Ee;
    const __nv_bfloat16* Ah = qh + abase;
    const __nv_bfloat16* Al = ql + abase;
    const __nv_bfloat16* Bh = kh + abase;
    const __nv_bfloat16* Bl = kl + abase;
    float* C = attn + (long)bz*Ll*Ll;
    const int row0 = blockIdx.y * 128, col0 = blockIdx.x * 128;
    const int wm = (wid & 3) * 32;
    const int wn = (wid >> 2) * 64;

    float acc[2][8][4];
#pragma unroll
    for (int i=0;i<2;i++)
#pragma unroll
        for (int j=0;j<8;j++)
#pragma unroll
            for (int t=0;t<4;t++) acc[i][j][t]=0.f;

    const int lr = lane & 15, lh = (lane >> 4) * 8;

    for (int k0 = 0; k0 < Ee; k0 += 32) {
#pragma unroll
        for (int s = 0; s < 2; s++) {
            const int idx = s * 256 + tid;
            const int r = idx >> 2, c = (idx & 3) * 8;
            *(uint4*)&sAh[r][c] = *(const uint4*)(Ah + (long)(row0+r)*Dd + k0 + c);
            *(uint4*)&sAl[r][c] = *(const uint4*)(Al + (long)(row0+r)*Dd + k0 + c);
            *(uint4*)&sBh[r][c] = *(const uint4*)(Bh + (long)(col0+r)*Dd + k0 + c);
            *(uint4*)&sBl[r][c] = *(const uint4*)(Bl + (long)(col0+r)*Dd + k0 + c);
        }
        __syncthreads();

#pragma unroll
        for (int kk = 0; kk < 32; kk += 16) {
            unsigned ahf[2][4], alf[2][4];
#pragma unroll
            for (int mi = 0; mi < 2; mi++) {
                ldm_x4(ahf[mi], sptr(&sAh[wm + mi*16 + lr][kk + lh]));
                ldm_x4(alf[mi], sptr(&sAl[wm + mi*16 + lr][kk + lh]));
            }
#pragma unroll
            for (int half = 0; half < 2; half++) {
                unsigned bh[4][2], bl[4][2];
#pragma unroll
                for (int p = 0; p < 2; p++) {
                    unsigned f[4];
                    ldm_x4(f, sptr(&sBh[wn + half*32 + p*16 + lr][kk + lh]));
                    bh[2*p+0][0]=f[0]; bh[2*p+0][1]=f[2];
                    bh[2*p+1][0]=f[1]; bh[2*p+1][1]=f[3];
                    ldm_x4(f, sptr(&sBl[wn + half*32 + p*16 + lr][kk + lh]));
                    bl[2*p+0][0]=f[0]; bl[2*p+0][1]=f[2];
                    bl[2*p+1][0]=f[1]; bl[2*p+1][1]=f[3];
                }
#pragma unroll
                for (int mi = 0; mi < 2; mi++)
#pragma unroll
                    for (int nj = 0; nj < 4; nj++) {
                        float* a = acc[mi][half*4 + nj];
                        mma16816(a, ahf[mi], bh[nj][0], bh[nj][1]);
                        mma16816(a, ahf[mi], bl[nj][0], bl[nj][1]);
                        mma16816(a, alf[mi], bh[nj][0], bh[nj][1]);
                    }
            }
        }
        __syncthreads();
    }

#pragma unroll
    for (int mi = 0; mi < 2; mi++) {
        const int r = row0 + wm + mi*16 + (lane >> 2);
#pragma unroll
        for (int ni = 0; ni < 8; ni++) {
            const int c = col0 + wn + (ni>>2)*32 + (ni&3)*8 + (lane & 3)*2;
            *(float2*)(C + (long)r*Ll + c) =
                make_float2(acc[mi][ni][0]*0.125f, acc[mi][ni][1]*0.125f);
            *(float2*)(C + (long)(r+8)*Ll + c) =
                make_float2(acc[mi][ni][2]*0.125f, acc[mi][ni][3]*0.125f);
        }
    }
}

// ================= attn @ v via mma: per (b,h), BM=128, BN=64 ==============
__global__ __launch_bounds__(256) void attnv_mma(
    const __nv_bfloat16* __restrict__ ah, const __nv_bfloat16* __restrict__ al,
    const __nv_bfloat16* __restrict__ vth, const __nv_bfloat16* __restrict__ vtl,
    __nv_bfloat16* __restrict__ oh, __nv_bfloat16* __restrict__ ol)
{
    __shared__ __nv_bfloat16 sAh[128][40], sAl[128][40];
    __shared__ __nv_bfloat16 sBh[64][40],  sBl[64][40];
    const int tid = threadIdx.x;
    const int wid = tid >> 5, lane = tid & 31;
    const int bz = blockIdx.z;
    const __nv_bfloat16* Abh = ah + (long)bz*Ll*Ll;
    const __nv_bfloat16* Abl = al + (long)bz*Ll*Ll;
    const __nv_bfloat16* Bbh = vth + (long)bz*Ee*Ll;
    const __nv_bfloat16* Bbl = vtl + (long)bz*Ee*Ll;
    const long obase = (long)(bz>>3)*Ll*Dd + (bz&7)*Ee;
    const int row0 = blockIdx.y * 128;
    const int wm = (wid & 3) * 32;
    const int wn = (wid >> 2) * 32;

    float acc[2][4][4];
#pragma unroll
    for (int i=0;i<2;i++)
#pragma unroll
        for (int j=0;j<4;j++)
#pragma unroll
            for (int t=0;t<4;t++) acc[i][j][t]=0.f;

    const int lr = lane & 15, lh = (lane >> 4) * 8;

    for (int k0 = 0; k0 < Ll; k0 += 32) {
#pragma unroll
        for (int s = 0; s < 2; s++) {
            const int idx = s * 256 + tid;
            const int r = idx >> 2, c = (idx & 3) * 8;
            *(uint4*)&sAh[r][c] = *(const uint4*)(Abh + (long)(row0+r)*Ll + k0 + c);
            *(uint4*)&sAl[r][c] = *(const uint4*)(Abl + (long)(row0+r)*Ll + k0 + c);
        }
        {
            const int r = tid >> 2, c = (tid & 3) * 8;
            *(uint4*)&sBh[r][c] = *(const uint4*)(Bbh + (long)r*Ll + k0 + c);
            *(uint4*)&sBl[r][c] = *(const uint4*)(Bbl + (long)r*Ll + k0 + c);
        }
        __syncthreads();

#pragma unroll
        for (int kk = 0; kk < 32; kk += 16) {
            unsigned ahf[2][4], alf[2][4];
#pragma unroll
            for (int mi = 0; mi < 2; mi++) {
                ldm_x4(ahf[mi], sptr(&sAh[wm + mi*16 + lr][kk + lh]));
                ldm_x4(alf[mi], sptr(&sAl[wm + mi*16 + lr][kk + lh]));
            }
            unsigned bh[4][2], bl[4][2];
#pragma unroll
            for (int p = 0; p < 2; p++) {
                unsigned f[4];
                ldm_x4(f, sptr(&sBh[wn + p*16 + lr][kk + lh]));
                bh[2*p+0][0]=f[0]; bh[2*p+0][1]=f[2];
                bh[2*p+1][0]=f[1]; bh[2*p+1][1]=f[3];
                ldm_x4(f, sptr(&sBl[wn + p*16 + lr][kk + lh]));
                bl[2*p+0][0]=f[0]; bl[2*p+0][1]=f[2];
                bl[2*p+1][0]=f[1]; bl[2*p+1][1]=f[3];
            }
#pragma unroll
            for (int mi = 0; mi < 2; mi++)
#pragma unroll
                for (int nj = 0; nj < 4; nj++) {
                    float* a = acc[mi][nj];
                    mma16816(a, ahf[mi], bh[nj][0], bh[nj][1]);
                    mma16816(a, ahf[mi], bl[nj][0], bl[nj][1]);
                    mma16816(a, alf[mi], bh[nj][0], bh[nj][1]);
                }
        }
        __syncthreads();
    }

#pragma unroll
    for (int mi = 0; mi < 2; mi++) {
        const int r = row0 + wm + mi*16 + (lane >> 2);
#pragma unroll
        for (int nj = 0; nj < 4; nj++) {
            const int c = wn + nj*8 + (lane & 3)*2;
            __nv_bfloat162 h2, l2;
            split2(acc[mi][nj][0], h2.x, l2.x);
            split2(acc[mi][nj][1], h2.y, l2.y);
            *(__nv_bfloat162*)(oh + obase + (long)r*Dd + c) = h2;
            *(__nv_bfloat162*)(ol + obase + (long)r*Dd + c) = l2;
            split2(acc[mi][nj][2], h2.x, l2.x);
            split2(acc[mi][nj][3], h2.y, l2.y);
            *(__nv_bfloat162*)(oh + obase + (long)(r+8)*Dd + c) = h2;
            *(__nv_bfloat162*)(ol + obase + (long)(r+8)*Dd + c) = l2;
        }
    }
}

// ================= split conversions =======================================
__global__ __launch_bounds__(256) void split_act(
    const float* __restrict__ x, __nv_bfloat16* __restrict__ h,
    __nv_bfloat16* __restrict__ l)
{
    const int i = blockIdx.x * 256 + threadIdx.x;
    const float v = x[i];
    __nv_bfloat16 hi, lo; split2(v, hi, lo);
    h[i] = hi; l[i] = lo;
}

// W [K][N] fp32 -> Wt hi/lo bf16 [N][K]
__global__ __launch_bounds__(256) void split_wt(
    const float* __restrict__ W, int Kdim, int Ndim,
    __nv_bfloat16* __restrict__ h, __nv_bfloat16* __restrict__ l)
{
    __shared__ float t[32][33];
    const int tx = threadIdx.x, ty = threadIdx.y;
    const int n0 = blockIdx.x * 32, k0 = blockIdx.y * 32;
#pragma unroll
    for (int j = 0; j < 4; j++)
        t[ty + 8 * j][tx] = W[(long)(k0 + ty + 8 * j) * Ndim + n0 + tx];
    __syncthreads();
#pragma unroll
    for (int j = 0; j < 4; j++) {
        const float v = t[tx][ty + 8 * j];
        __nv_bfloat16 hi, lo; split2(v, hi, lo);
        const long oidx = (long)(n0 + ty + 8 * j) * Kdim + k0 + tx;
        h[oidx] = hi; l[oidx] = lo;
    }
}

// v pair [b*1024+s][h*64+e] -> vT pair [(b*8+h)*64+e][s]
__global__ void vtrans(
    const __nv_bfloat16* __restrict__ vh, const __nv_bfloat16* __restrict__ vl,
    __nv_bfloat16* __restrict__ vth, __nv_bfloat16* __restrict__ vtl)
{
    __shared__ __nv_bfloat16 th[32][33], tl[32][33];
    const int tx = threadIdx.x, ty = threadIdx.y;   // (32, 8)
    const int bh = blockIdx.z;
    const int b = bh >> 3, h = bh & 7;
    const int s0 = blockIdx.x * 32, e0 = blockIdx.y * 32;
    const long ibase = (long)b*Ll*Dd + h*Ee;
#pragma unroll
    for (int j = 0; j < 4; j++) {
        const long off = ibase + (long)(s0 + ty + 8*j)*Dd + e0 + tx;
        th[ty+8*j][tx] = vh[off];
        tl[ty+8*j][tx] = vl[off];
    }
    __syncthreads();
    const long obase = (long)bh*Ee*Ll;
#pragma unroll
    for (int j = 0; j < 4; j++) {
        const long off = obase + (long)(e0 + ty + 8*j)*Ll + s0 + tx;
        vth[off] = th[tx][ty+8*j];
        vtl[off] = tl[tx][ty+8*j];
    }
}

// ------- softmax rows of 1024 (float4 I/O), in place + bf16 pair output ----
__global__ __launch_bounds__(256) void softmax_split(
    float* __restrict__ a, __nv_bfloat16* __restrict__ ah,
    __nv_bfloat16* __restrict__ al)
{
    const long row = blockIdx.x;
    float* p = a + row * (long)Ll;
    __nv_bfloat16* ph = ah + row * (long)Ll;
    __nv_bfloat16* pl = al + row * (long)Ll;
    const int tid = threadIdx.x;

    float4 v4 = *(float4*)(p + tid * 4);
    float m = fmaxf(fmaxf(v4.x, v4.y), fmaxf(v4.z, v4.w));
#pragma unroll
    for (int off=16; off; off>>=1) m = fmaxf(m, __shfl_xor_sync(0xffffffffu, m, off));
    __shared__ float sm[8], ss[8];
    const int w = tid >> 5, lane = tid & 31;
    if (lane==0) sm[w] = m;
    __syncthreads();
    m = sm[0];
#pragma unroll
    for (int i=1;i<8;i++) m = fmaxf(m, sm[i]);
    v4.x = __expf(v4.x - m); v4.y = __expf(v4.y - m);
    v4.z = __expf(v4.z - m); v4.w = __expf(v4.w - m);
    float s = v4.x + v4.y + v4.z + v4.w;
#pragma unroll
    for (int off=16; off; off>>=1) s += __shfl_xor_sync(0xffffffffu, s, off);
    if (lane==0) ss[w] = s;
    __syncthreads();
    s = 0.f;
#pragma unroll
    for (int i=0;i<8;i++) s += ss[i];
    const float inv = 1.f / s;
    v4.x *= inv; v4.y *= inv; v4.z *= inv; v4.w *= inv;
    *(float4*)(p + tid * 4) = v4;
    __nv_bfloat162 h01, l01, h23, l23;
    split2(v4.x, h01.x, l01.x); split2(v4.y, h01.y, l01.y);
    split2(v4.z, h23.x, l23.x); split2(v4.w, h23.y, l23.y);
    *(__nv_bfloat162*)(ph + tid*4)     = h01;
    *(__nv_bfloat162*)(ph + tid*4 + 2) = h23;
    *(__nv_bfloat162*)(pl + tid*4)     = l01;
    *(__nv_bfloat162*)(pl + tid*4 + 2) = l23;
}

// ---------------- out = LayerNorm(xa + xb) (+ optional bf16 pair) ----------
__global__ __launch_bounds__(128) void add_ln(
    const float* __restrict__ xa, const float* __restrict__ xb,
    const float* __restrict__ g, const float* __restrict__ bt,
    float* __restrict__ out, __nv_bfloat16* __restrict__ oh,
    __nv_bfloat16* __restrict__ ol)
{
    const int row = blockIdx.x, tid = threadIdx.x;
    const float* pa = xa + (long)row*Dd;
    const float* pb = xb + (long)row*Dd;
    float v[4]; float s1=0.f, s2=0.f;
#pragma unroll
    for (int i=0;i<4;i++){ int c = tid + 128*i; v[i] = pa[c] + pb[c]; s1 += v[i]; s2 += v[i]*v[i]; }
#pragma unroll
    for (int off=16; off; off>>=1){
        s1 += __shfl_xor_sync(0xffffffffu, s1, off);
        s2 += __shfl_xor_sync(0xffffffffu, s2, off);
    }
    __shared__ float r1[4], r2[4];
    const int w = tid >> 5, lane = tid & 31;
    if (lane==0){ r1[w]=s1; r2[w]=s2; }
    __syncthreads();
    s1 = r1[0]+r1[1]+r1[2]+r1[3];
    s2 = r2[0]+r2[1]+r2[2]+r2[3];
    const float mean = s1 * (1.f/Dd);
    const float var  = s2 * (1.f/Dd) - mean*mean;
    const float rstd = rsqrtf(var + 1e-5f);
    float* po = out + (long)row*Dd;
#pragma unroll
    for (int i=0;i<4;i++){
        const int c = tid + 128*i;
        const float val = (v[i]-mean)*rstd*g[c] + bt[c];
        po[c] = val;
        if (oh) {
            __nv_bfloat16 hi, lo; split2(val, hi, lo);
            oh[(long)row*Dd + c] = hi;
            ol[(long)row*Dd + c] = lo;
        }
    }
}

// ============ 64x64 GEMM (Wdt) =============================================
__global__ __launch_bounds__(256) void gemm64(
    const float* __restrict__ A, int lda,
    const float* __restrict__ W, int ldw,
    const float* __restrict__ bias,
    float* __restrict__ C, int ldc, int K, int act)
{
    __shared__ float As[16][64];
    __shared__ float Ws[16][68];
    const int tid = threadIdx.x;
    const int row0 = blockIdx.y * 64;
    const int col0 = blockIdx.x * 64;
    const int ar = tid >> 2, ac = (tid & 3) * 4;
    const int br = tid >> 4, bc = (tid & 15) * 4;
    const int tm = (tid & 15) * 4, tn = (tid >> 4) * 4;
    float acc[4][4];
#pragma unroll
    for (int i=0;i<4;i++)
#pragma unroll
        for (int j=0;j<4;j++) acc[i][j]=0.f;

    for (int k0 = 0; k0 < K; k0 += 16) {
        float4 a4 = *(const float4*)(A + (long)(row0+ar)*lda + k0 + ac);
        As[ac+0][ar]=a4.x; As[ac+1][ar]=a4.y; As[ac+2][ar]=a4.z; As[ac+3][ar]=a4.w;
        float4 b4 = *(const float4*)(W + (long)(k0+br)*ldw + col0 + bc);
        *(float4*)&Ws[br][bc] = b4;
        __syncthreads();
#pragma unroll
        for (int k=0;k<16;k++){
            float a[4], b[4];
#pragma unroll
            for (int i=0;i<4;i++) a[i]=As[k][tm+i];
#pragma unroll
            for (int j=0;j<4;j++) b[j]=Ws[k][tn+j];
#pragma unroll
            for (int i=0;i<4;i++)
#pragma unroll
                for (int j=0;j<4;j++) acc[i][j]=fmaf(a[i],b[j],acc[i][j]);
        }
        __syncthreads();
    }
#pragma unroll
    for (int j=0;j<4;j++){
        int c = col0 + tn + j;
        float bvv = bias ? bias[c] : 0.f;
#pragma unroll
        for (int i=0;i<4;i++){
            float vv = acc[i][j] + bvv;
            if (act == 1) vv = (vv > 20.f) ? vv : log1pf(__expf(vv));
            C[(long)(row0+tm+i)*ldc + c] = vv;
        }
    }
}

// ============ 32x64 GEMM for Wx (higher occupancy: 128 CTAs) ===============
__global__ __launch_bounds__(256) void gemm32(
    const float* __restrict__ A, int lda,
    const float* __restrict__ W, int ldw,
    float* __restrict__ C, int ldc, int K)
{
    __shared__ float As[16][33];
    __shared__ float Ws[16][68];
    const int tid = threadIdx.x;
    const int row0 = blockIdx.y * 32;
    const int ar = tid >> 3, ac = (tid & 7) * 2;      // 32 rows x 16 k, 2/thread
    const int br = tid >> 4, bc = (tid & 15) * 4;     // 16 k x 64 n, 4/thread
    const int tm = (tid & 15) * 2, tn = (tid >> 4) * 4;
    float acc[2][4];
#pragma unroll
    for (int i=0;i<2;i++)
#pragma unroll
        for (int j=0;j<4;j++) acc[i][j]=0.f;

    for (int k0 = 0; k0 < K; k0 += 16) {
        float2 a2 = *(const float2*)(A + (long)(row0+ar)*lda + k0 + ac);
        As[ac+0][ar]=a2.x; As[ac+1][ar]=a2.y;
        float4 b4 = *(const float4*)(W + (long)(k0+br)*ldw + bc);
        *(float4*)&Ws[br][bc] = b4;
        __syncthreads();
#pragma unroll
        for (int k=0;k<16;k++){
            float a[2], b[4];
#pragma unroll
            for (int i=0;i<2;i++) a[i]=As[k][tm+i];
#pragma unroll
            for (int j=0;j<4;j++) b[j]=Ws[k][tn+j];
#pragma unroll
            for (int i=0;i<2;i++)
#pragma unroll
                for (int j=0;j<4;j++) acc[i][j]=fmaf(a[i],b[j],acc[i][j]);
        }
        __syncthreads();
    }
#pragma unroll
    for (int i=0;i<2;i++){
        float4 o1 = make_float4(acc[i][0], acc[i][1], acc[i][2], acc[i][3]);
        *(float4*)(C + (long)(row0+tm+i)*ldc + tn) = o1;
    }
}

// ---------------- depthwise causal conv (K=4) + bias + silu ----------------
__global__ __launch_bounds__(256) void conv_silu_k(
    const float* __restrict__ xz, const float* __restrict__ w,
    const float* __restrict__ cb, float* __restrict__ xc)
{
    const long idx = (long)blockIdx.x*256 + threadIdx.x;
    const int d = (int)(idx & (DINc-1));
    const long row = idx >> 10;
    const int l = (int)(row & (Ll-1));
    float acc = cb[d];
#pragma unroll
    for (int j=0;j<4;j++) {
        int ll = l - 3 + j;
        if (ll >= 0)
            acc = fmaf(xz[(row-3+j)*(2*DINc) + d], w[d*4+j], acc);
    }
    xc[idx] = acc / (1.f + __expf(-acc));
}

// ---------- selective scan, depth-8 load pipeline, bf16 pair output --------
#define PFD 8
__global__ __launch_bounds__(128) void scan_k(
    const float* __restrict__ dt, const float* __restrict__ xc,
    const float* __restrict__ dbl, const float* __restrict__ xz,
    const float* __restrict__ Alog, const float* __restrict__ Dp,
    __nv_bfloat16* __restrict__ yh, __nv_bfloat16* __restrict__ yl)
{
    const int tid = threadIdx.x;
    const int n  = tid & 15;
    const int dl = tid >> 4;
    const int b  = blockIdx.x >> 7;
    const int d  = (blockIdx.x & 127)*8 + dl;
    const float Aa = -__expf(Alog[d*Nn + n]);
    const float Dv = Dp[d];
    float h = 0.f;
    const long base = (long)b * Ll;

    float rdt[PFD], rxc[PFD], rB[PFD], rC[PFD], rz[PFD];
#pragma unroll
    for (int i = 0; i < PFD; i++) {
        const long r = base + i;
        rdt[i] = dt[r*DINc + d];
        rxc[i] = xc[r*DINc + d];
        rB[i]  = dbl[r*64 + 32 + n];
        rC[i]  = dbl[r*64 + 48 + n];
        rz[i]  = xz[r*(2*DINc) + DINc + d];
    }

    for (int t0 = 0; t0 < Ll; t0 += PFD) {
        float ndt[PFD], nxc[PFD], nB[PFD], nC[PFD], nz[PFD];
        const bool more = (t0 + PFD) < Ll;
        if (more) {
#pragma unroll
            for (int i = 0; i < PFD; i++) {
                const long r = base + t0 + PFD + i;
                ndt[i] = dt[r*DINc + d];
                nxc[i] = xc[r*DINc + d];
                nB[i]  = dbl[r*64 + 32 + n];
                nC[i]  = dbl[r*64 + 48 + n];
                nz[i]  = xz[r*(2*DINc) + DINc + d];
            }
        }
#pragma unroll
        for (int i = 0; i < PFD; i++) {
            const float dA = __expf(rdt[i] * Aa);
            h = fmaf(h, dA, rdt[i] * rxc[i] * rB[i]);
            float p = h * rC[i];
            p += __shfl_xor_sync(0xffffffffu, p, 8);
            p += __shfl_xor_sync(0xffffffffu, p, 4);
            p += __shfl_xor_sync(0xffffffffu, p, 2);
            p += __shfl_xor_sync(0xffffffffu, p, 1);
            if (n == 0) {
                const float sz = rz[i] / (1.f + __expf(-rz[i]));
                const float val = (p + rxc[i] * Dv) * sz;
                __nv_bfloat16 hi, lo; split2(val, hi, lo);
                yh[(base + t0 + i)*DINc + d] = hi;
                yl[(base + t0 + i)*DINc + d] = lo;
            }
        }
        if (more) {
#pragma unroll
            for (int i = 0; i < PFD; i++) {
                rdt[i]=ndt[i]; rxc[i]=nxc[i]; rB[i]=nB[i]; rC[i]=nC[i]; rz[i]=nz[i];
            }
        }
    }
}

// ---------------- launch ----------------------------------------------------
extern "C" void kernel_launch(void* const* d_in, const int* in_sizes, int n_in,
                              void* d_out, int out_size)
{
    const float* x    = (const float*)d_in[0];
    const float* Wq   = (const float*)d_in[1];
    const float* bq   = (const float*)d_in[2];
    const float* Wk   = (const float*)d_in[3];
    const float* bk   = (const float*)d_in[4];
    const float* Wv   = (const float*)d_in[5];
    const float* bv   = (const float*)d_in[6];
    const float* Wo   = (const float*)d_in[7];
    const float* bo   = (const float*)d_in[8];
    const float* ln1g = (const float*)d_in[9];
    const float* ln1b = (const float*)d_in[10];
    const float* ln2g = (const float*)d_in[11];
    const float* ln2b = (const float*)d_in[12];
    const float* Win  = (const float*)d_in[13];
    const float* cw   = (const float*)d_in[14];
    const float* cb   = (const float*)d_in[15];
    const float* Wx   = (const float*)d_in[16];
    const float* Wdt  = (const float*)d_in[17];
    const float* bdt  = (const float*)d_in[18];
    const float* Alog = (const float*)d_in[19];
    const float* Dp   = (const float*)d_in[20];
    const float* Wout = (const float*)d_in[21];

    float* out  = (float*)d_out;
    float* attn = out + (size_t)Bb*Ll*Dd;

    float *t1,*x1,*xz,*xc,*db,*dtb,*y;
    cudaGetSymbolAddress((void**)&t1, g_t1);
    cudaGetSymbolAddress((void**)&x1, g_x1);
    cudaGetSymbolAddress((void**)&xz, g_xz);
    cudaGetSymbolAddress((void**)&xc, g_xc);
    cudaGetSymbolAddress((void**)&db, g_db);
    cudaGetSymbolAddress((void**)&dtb,g_dt);
    cudaGetSymbolAddress((void**)&y,  g_y);

    __nv_bfloat16 *xh,*xl,*qh,*ql,*kh,*kl,*vh,*vl,*vth,*vtl,*ah,*al,*oh,*ol,*x1h,*x1l,*yah,*yal;
    __nv_bfloat16 *Wqh,*Wql,*Wkh,*Wkl,*Wvh,*Wvl,*Woh,*Wol,*Wih,*Wil,*Wuh,*Wul;
    cudaGetSymbolAddress((void**)&xh,  g_xh);  cudaGetSymbolAddress((void**)&xl,  g_xl);
    cudaGetSymbolAddress((void**)&qh,  g_qh);  cudaGetSymbolAddress((void**)&ql,  g_ql);
    cudaGetSymbolAddress((void**)&kh,  g_kh);  cudaGetSymbolAddress((void**)&kl,  g_kl);
    cudaGetSymbolAddress((void**)&vh,  g_vh);  cudaGetSymbolAddress((void**)&vl,  g_vl);
    cudaGetSymbolAddress((void**)&vth, g_vth); cudaGetSymbolAddress((void**)&vtl, g_vtl);
    cudaGetSymbolAddress((void**)&ah,  g_ah);  cudaGetSymbolAddress((void**)&al,  g_al);
    cudaGetSymbolAddress((void**)&oh,  g_oh);  cudaGetSymbolAddress((void**)&ol,  g_ol);
    cudaGetSymbolAddress((void**)&x1h, g_x1h); cudaGetSymbolAddress((void**)&x1l, g_x1l);
    cudaGetSymbolAddress((void**)&yah, g_yah); cudaGetSymbolAddress((void**)&yal, g_yal);
    cudaGetSymbolAddress((void**)&Wqh, g_Wqh); cudaGetSymbolAddress((void**)&Wql, g_Wql);
    cudaGetSymbolAddress((void**)&Wkh, g_Wkh); cudaGetSymbolAddress((void**)&Wkl, g_Wkl);
    cudaGetSymbolAddress((void**)&Wvh, g_Wvh); cudaGetSymbolAddress((void**)&Wvl, g_Wvl);
    cudaGetSymbolAddress((void**)&Woh, g_Woh); cudaGetSymbolAddress((void**)&Wol, g_Wol);
    cudaGetSymbolAddress((void**)&Wih, g_Wih); cudaGetSymbolAddress((void**)&Wil, g_Wil);
    cudaGetSymbolAddress((void**)&Wuh, g_Wuh); cudaGetSymbolAddress((void**)&Wul, g_Wul);

    // weight conversions (transpose + hi/lo split)
    split_wt<<<dim3(Dd/32, Dd/32), dim3(32,8)>>>(Wq, Dd, Dd, Wqh, Wql);
    split_wt<<<dim3(Dd/32, Dd/32), dim3(32,8)>>>(Wk, Dd, Dd, Wkh, Wkl);
    split_wt<<<dim3(Dd/32, Dd/32), dim3(32,8)>>>(Wv, Dd, Dd, Wvh, Wvl);
    split_wt<<<dim3(Dd/32, Dd/32), dim3(32,8)>>>(Wo, Dd, Dd, Woh, Wol);
    split_wt<<<dim3(2*DINc/32, Dd/32), dim3(32,8)>>>(Win, Dd, 2*DINc, Wih, Wil);
    split_wt<<<dim3(Dd/32, DINc/32), dim3(32,8)>>>(Wout, DINc, Dd, Wuh, Wul);

    // x split + QKV (mma, bf16-pair outputs)
    split_act<<<(Mrows*Dd)/256, 256>>>(x, xh, xl);
    gemm_mma<<<dim3(Dd/128, Mrows/128), 256>>>(xh, xl, Wqh, Wql, bq, nullptr, qh, ql, Dd, Dd);
    gemm_mma<<<dim3(Dd/128, Mrows/128), 256>>>(xh, xl, Wkh, Wkl, bk, nullptr, kh, kl, Dd, Dd);
    gemm_mma<<<dim3(Dd/128, Mrows/128), 256>>>(xh, xl, Wvh, Wvl, bv, nullptr, vh, vl, Dd, Dd);
    vtrans<<<dim3(Ll/32, Ee/32, Bb*Hh), dim3(32,8)>>>(vh, vl, vth, vtl);

    // attention
    scores_mma<<<dim3(Ll/128, Ll/128, Bb*Hh), 256>>>(qh, ql, kh, kl, attn);
    softmax_split<<<Bb*Hh*Ll, 256>>>(attn, ah, al);
    attnv_mma<<<dim3(1, Ll/128, Bb*Hh), 256>>>(ah, al, vth, vtl, oh, ol);

    // o @ Wo + bo (mma) ; x1 = LN(x + .) with pair output
    gemm_mma<<<dim3(Dd/128, Mrows/128), 256>>>(oh, ol, Woh, Wol, bo, t1, nullptr, nullptr, Dd, Dd);
    add_ln<<<Mrows, 128>>>(x, t1, ln1g, ln1b, x1, x1h, x1l);

    // mamba in-proj (mma, N=2048)
    gemm_mma<<<dim3(2*DINc/128, Mrows/128), 256>>>(x1h, x1l, Wih, Wil, nullptr, xz, nullptr, nullptr, 2*DINc, Dd);

    // conv + silu
    conv_silu_k<<<(Mrows*DINc)/256, 256>>>(xz, cw, cb, xc);
    // dbl = xc @ Wx   (N=64, K=1024) — 32-row tiles: 128 CTAs
    gemm32<<<dim3(1, Mrows/32), 256>>>(xc, DINc, Wx, 64, db, 64, DINc);
    // dt = softplus(dbl[:, :32] @ Wdt + bdt)
    gemm64<<<dim3(DINc/64, Mrows/64), 256>>>(db, 64, Wdt, DINc, bdt, dtb, DINc, Rr, 1);
    // selective scan -> ya bf16 pair
    scan_k<<<Bb*(DINc/8), 128>>>(dtb, xc, db, xz, Alog, Dp, yah, yal);

    // out-proj (mma, K=1024) + final LN
    gemm_mma<<<dim3(Dd/128, Mrows/128), 256>>>(yah, yal, Wuh, Wul, nullptr, y, nullptr, nullptr, Dd, DINc);
    add_ln<<<Mrows, 128>>>(x1, y, ln2g, ln2b, out, nullptr, nullptr);

    (void)in_sizes; (void)n_in; (void)out_size;
}